// round 12
// baseline (speedup 1.0000x reference)
#include <cuda_runtime.h>
#include <cuda_fp16.h>
#include <stdint.h>
#include <math.h>

#define BB 8
#define TT 1024
#define DM 1024
#define NH 8
#define DK 128
#define MROWS (BB*TT)   /* 8192 */

// ---------------- scratch (device globals; no cudaMalloc allowed) ----------
__device__ __half g_q2 [(size_t)MROWS * DM];        // 16 MB
__device__ __half g_k2 [(size_t)MROWS * DM];        // 16 MB
__device__ __half g_v2 [(size_t)MROWS * DM];        // 16 MB
__device__ __half g_wqh[(size_t)NH * DM * DK];      // 2 MB  [h][128][1024]
__device__ __half g_wkh[(size_t)NH * DM * DK];      // 2 MB
__device__ __half g_wvh[(size_t)DM * DK];           // [128][1024]
__device__ __half g_woh[(size_t)DM * DK];           // [1024][128]
__device__ __half g_qh [(size_t)MROWS * DM];        // 16 MB  qh (A of scores)
__device__ __half g_khh[(size_t)MROWS * DM];        // 16 MB  kh (B of scores)
__device__ __half g_vth[(size_t)MROWS * DK];        // 2 MB   vhT [b][128][1024]
__device__ __half g_sc [(size_t)NH * BB * TT * TT]; // 134 MB scores fp16 -> P in place
__device__ __half g_oh [(size_t)NH * MROWS * DK];   // 16 MB  per-head O (fp16)
__device__ __half g_om [(size_t)MROWS * DK];        // 2 MB   head-mean fp16

// ======================= helpers ==============================
__device__ __forceinline__ uint32_t smem_u32(const void* p) {
    uint32_t a;
    asm("{ .reg .u64 t; cvta.to.shared.u64 t, %1; cvt.u32.u64 %0, t; }"
        : "=r"(a) : "l"(p));
    return a;
}
__device__ __forceinline__ uint32_t sw128(uint32_t off) {
    return off ^ ((off >> 3) & 0x70);
}
__device__ __forceinline__ void ldm4(uint32_t* d, uint32_t addr) {
    asm volatile("ldmatrix.sync.aligned.m8n8.x4.shared.b16 {%0,%1,%2,%3}, [%4];"
                 : "=r"(d[0]), "=r"(d[1]), "=r"(d[2]), "=r"(d[3]) : "r"(addr));
}
__device__ __forceinline__ void mma16816(float* c, const uint32_t* a, const uint32_t* b) {
    asm volatile(
        "mma.sync.aligned.m16n8k16.row.col.f32.f16.f16.f32 "
        "{%0,%1,%2,%3}, {%4,%5,%6,%7}, {%8,%9}, {%0,%1,%2,%3};"
        : "+f"(c[0]), "+f"(c[1]), "+f"(c[2]), "+f"(c[3])
        : "r"(a[0]), "r"(a[1]), "r"(a[2]), "r"(a[3]), "r"(b[0]), "r"(b[1]));
}
#define CP16(sa, ga) \
    asm volatile("cp.async.ca.shared.global [%0], [%1], 16;" :: "r"(sa), "l"(ga))
#define CP_COMMIT() asm volatile("cp.async.commit_group;" ::: "memory")
#define CP_WAIT2()  asm volatile("cp.async.wait_group 2;"  ::: "memory")

// ============================================================================
// Templated fp16 HMMA GEMM:  D[128x128 tile] = A(MxK) * B(NxK)^T * cscale
// 3-stage cp.async pipeline (2x16KB per stage = 96KB smem, 2 CTAs/SM).
// MODE 0: plain.  MODE 1: causal score tile skip.  MODE 2: causal K-limit.
// OUT 0: fp32.  OUT 1: fp16.  OUT 2: fp16 transposed (vhT[b][n][t]).
// (Exact R9 mainloop — measured 62.7us / tensor 45% on the 8192x1024x1024.)
// ============================================================================
template<int MODE, int OUT>
__global__ __launch_bounds__(256, 2)
void gemm_t(const __half* __restrict__ Ah, const __half* __restrict__ Bh,
            void* __restrict__ Cout, float cscale,
            int K, int lda, int ldb, int ldc,
            long long aS1, long long aS2, long long bS1, long long bS2,
            long long cS1, long long cS2)
{
    extern __shared__ char sm[];
    const int tid  = threadIdx.x;
    const int wid  = tid >> 5;
    const int lane = tid & 31;
    const int row0 = blockIdx.y * 128;
    const int col0 = blockIdx.x * 128;
    if (MODE == 1 && col0 >= row0 + 128) return;     // fully above diagonal

    const int z1 = blockIdx.z >> 3, z2 = blockIdx.z & 7;
    const __half* Ab  = Ah + (size_t)z1 * aS1 + (size_t)z2 * aS2;
    const __half* Bhb = Bh + (size_t)z1 * bS1 + (size_t)z2 * bS2;

    const int Keff = (MODE == 2) ? (row0 + 128 < K ? row0 + 128 : K) : K;
    const int nCh  = Keff >> 6;                      // 64-wide K chunks (>=2)

    const uint32_t sb = smem_u32(sm);

#define FILL(cc) do {                                                         \
        uint32_t stb = sb + (uint32_t)((cc) % 3) * 32768;                     \
        const size_t k0 = (size_t)(cc) << 6;                                  \
        _Pragma("unroll")                                                     \
        for (int i = 0; i < 4; i++) {                                         \
            int id = tid + 256 * i;                                           \
            int rr = id >> 3, sg = id & 7;                                    \
            uint32_t sw = sw128((uint32_t)rr * 128 + sg * 16);                \
            CP16(stb + sw,         Ab  + (size_t)(row0 + rr) * lda + k0 + sg * 8); \
            CP16(stb + 16384 + sw, Bhb + (size_t)(col0 + rr) * ldb + k0 + sg * 8); \
        }                                                                     \
    } while (0)

    // ---- warp tiling: 2 (m) x 4 (n) warps; each 64 rows x 32 cols ----
    const int wm = (wid >> 2) * 64;
    const int wn = (wid & 3) * 32;

    uint32_t aBase[4], bBase[2];
#pragma unroll
    for (int mt = 0; mt < 4; mt++) {
        int r = wm + mt * 16 + ((lane >> 3) & 1) * 8 + (lane & 7);
        aBase[mt] = (uint32_t)r * 128 + (uint32_t)((lane >> 4) * 8) * 2;
    }
#pragma unroll
    for (int np = 0; np < 2; np++) {
        int r = wn + np * 16 + (lane >> 4) * 8 + (lane & 7);
        bBase[np] = (uint32_t)r * 128 + (uint32_t)(((lane >> 3) & 1) * 8) * 2;
    }

    float acc[4][4][4];
#pragma unroll
    for (int mt = 0; mt < 4; mt++)
#pragma unroll
        for (int nt = 0; nt < 4; nt++)
#pragma unroll
            for (int i = 0; i < 4; i++) acc[mt][nt][i] = 0.f;

    // ---- prologue: 3 stages in flight ----
#pragma unroll
    for (int p = 0; p < 3; p++) { if (p < nCh) FILL(p); CP_COMMIT(); }

    for (int c = 0; c < nCh; ++c) {
        CP_WAIT2();
        __syncthreads();
        const uint32_t tb = sb + (uint32_t)(c % 3) * 32768;
#pragma unroll
        for (int ks = 0; ks < 4; ks++) {
            const uint32_t kb2 = (uint32_t)ks * 32;
            uint32_t a[4][4], b2[2][4];
#pragma unroll
            for (int mt = 0; mt < 4; mt++)
                ldm4(a[mt], tb + sw128(aBase[mt] + kb2));
#pragma unroll
            for (int np = 0; np < 2; np++)
                ldm4(b2[np], tb + 16384 + sw128(bBase[np] + kb2));
#pragma unroll
            for (int mt = 0; mt < 4; mt++)
#pragma unroll
                for (int nt = 0; nt < 4; nt++)
                    mma16816(acc[mt][nt], a[mt], &b2[nt >> 1][(nt & 1) * 2]);
        }
        __syncthreads();                // all reads of buf (c%3) done
        int f = c + 3;
        if (f < nCh) FILL(f);
        CP_COMMIT();
    }
#undef FILL

    // ---- epilogue (single variant per instantiation) ----
#pragma unroll
    for (int mt = 0; mt < 4; mt++) {
        const int r = row0 + wm + mt * 16 + (lane >> 2);
#pragma unroll
        for (int nt = 0; nt < 4; nt++) {
            const int cc = col0 + wn + nt * 8 + (lane & 3) * 2;
            float a0 = acc[mt][nt][0], a1 = acc[mt][nt][1];
            float a2 = acc[mt][nt][2], a3 = acc[mt][nt][3];
            if (cscale != 1.f) { a0 *= cscale; a1 *= cscale; a2 *= cscale; a3 *= cscale; }
            if (OUT == 0) {
                float* Cb = (float*)Cout + (size_t)z1 * cS1 + (size_t)z2 * cS2;
                float* p = Cb + (size_t)r * ldc + cc;
                *(float2*)p = make_float2(a0, a1);
                *(float2*)(p + (size_t)8 * ldc) = make_float2(a2, a3);
            } else if (OUT == 1) {
                __half* Cb = (__half*)Cout + (size_t)z1 * cS1 + (size_t)z2 * cS2;
                *(__half2*)(Cb + (size_t)r * ldc + cc) = __floats2half2_rn(a0, a1);
                *(__half2*)(Cb + (size_t)(r + 8) * ldc + cc) = __floats2half2_rn(a2, a3);
            } else {   // vhT[b][n][t]: b = r>>10, t = r&1023
                __half* CT = (__half*)Cout;
                size_t b0 = (size_t)(r >> 10) * 131072 + (r & 1023);
                CT[b0 + (size_t)cc * 1024]       = __float2half_rn(a0);
                CT[b0 + (size_t)(cc + 1) * 1024] = __float2half_rn(a1);
                size_t b1 = (size_t)((r + 8) >> 10) * 131072 + ((r + 8) & 1023);
                CT[b1 + (size_t)cc * 1024]       = __float2half_rn(a2);
                CT[b1 + (size_t)(cc + 1) * 1024] = __float2half_rn(a3);
            }
        }
    }
}

// ============================================================================
// fp32 -> fp16 convert; blockIdx.y selects one of 3 (in,out) pairs
// ============================================================================
__global__ __launch_bounds__(256)
void conv_h3(const float* __restrict__ i0, __half* __restrict__ o0,
             const float* __restrict__ i1, __half* __restrict__ o1,
             const float* __restrict__ i2, __half* __restrict__ o2)
{
    const float* in  = blockIdx.y == 0 ? i0 : (blockIdx.y == 1 ? i1 : i2);
    __half*      out = blockIdx.y == 0 ? o0 : (blockIdx.y == 1 ? o1 : o2);
    const size_t i = ((size_t)blockIdx.x * 256 + threadIdx.x) * 4;
    float4 v = *(const float4*)(in + i);
    *(__half2*)(out + i)     = __floats2half2_rn(v.x, v.y);
    *(__half2*)(out + i + 2) = __floats2half2_rn(v.z, v.w);
}

// ============================================================================
// Merged weight transpose: z<8 Wq[z], z<16 Wk[z-8], z==16 Wv (all 1024x128),
// z==17 Wo (128x1024, block indices swapped).
// ============================================================================
__global__ __launch_bounds__(256)
void transpose_w18(const float* __restrict__ Wq, const float* __restrict__ Wk,
                   const float* __restrict__ Wv, const float* __restrict__ Wo,
                   __half* __restrict__ wqh, __half* __restrict__ wkh,
                   __half* __restrict__ wvh, __half* __restrict__ woh)
{
    __shared__ float t[32][33];
    const int z = blockIdx.z;
    const float* in; __half* out;
    int R, C, r0, c0;
    if (z < 8)       { in = Wq + (size_t)z * 131072;       out = wqh + (size_t)z * 131072;
                       R = 1024; C = 128; r0 = blockIdx.y * 32; c0 = blockIdx.x * 32; }
    else if (z < 16) { in = Wk + (size_t)(z - 8) * 131072; out = wkh + (size_t)(z - 8) * 131072;
                       R = 1024; C = 128; r0 = blockIdx.y * 32; c0 = blockIdx.x * 32; }
    else if (z == 16){ in = Wv;                            out = wvh;
                       R = 1024; C = 128; r0 = blockIdx.y * 32; c0 = blockIdx.x * 32; }
    else             { in = Wo;                            out = woh;
                       R = 128;  C = 1024; r0 = blockIdx.x * 32; c0 = blockIdx.y * 32; }
    const int tx = threadIdx.x, ty = threadIdx.y;
#pragma unroll
    for (int i = 0; i < 32; i += 8)
        t[ty + i][tx] = in[(size_t)(r0 + ty + i) * C + c0 + tx];
    __syncthreads();
#pragma unroll
    for (int i = 0; i < 32; i += 8)
        out[(size_t)(c0 + ty + i) * R + r0 + tx] = __float2half_rn(t[tx][ty + i]);
}

// ============================================================================
// Causal softmax: reads fp16 scores from sc ONLY up to the causal 128-block
// edge, writes the full fp32 attn row (zeros above diagonal) and fp16 P
// in-place into sc (up to the block edge = all PV reads). One warp per row.
// ============================================================================
__global__ __launch_bounds__(256)
void softmax_kernel(__half* __restrict__ sc, float* __restrict__ attn)
{
    const int gw   = blockIdx.x * 8 + (threadIdx.x >> 5);
    const int lane = threadIdx.x & 31;
    const int t    = gw & (TT - 1);
    __half2* srow = (__half2*)(sc + (size_t)gw * TT);
    float*   arow = attn + (size_t)gw * TT;
    const int plim = (((t >> 7) + 1) << 6);     // half2 units inside causal blocks

    float2 v[16];
    float m = -1e30f;
#pragma unroll
    for (int i = 0; i < 16; i++) {
        const int pi = i * 32 + lane;          // half2 index; s = 2*pi, 2*pi+1
        if (pi < plim) {
            __half2 h = srow[pi];
            v[i].x = (2 * pi     <= t) ? __low2float(h)  : -1e30f;
            v[i].y = (2 * pi + 1 <= t) ? __high2float(h) : -1e30f;
            m = fmaxf(m, fmaxf(v[i].x, v[i].y));
        } else { v[i].x = -1e30f; v[i].y = -1e30f; }
    }
#pragma unroll
    for (int o = 16; o; o >>= 1) m = fmaxf(m, __shfl_xor_sync(~0u, m, o));

    const float scale = 0.08838834764831845f;   // 1/sqrt(128)
    float sum = 0.f;
#pragma unroll
    for (int i = 0; i < 16; i++) {
        const int pi = i * 32 + lane;
        if (pi < plim) {
            float e0 = (2 * pi     <= t) ? __expf((v[i].x - m) * scale) : 0.f;
            float e1 = (2 * pi + 1 <= t) ? __expf((v[i].y - m) * scale) : 0.f;
            v[i].x = e0; v[i].y = e1;
            sum += e0 + e1;
        }
    }
#pragma unroll
    for (int o = 16; o; o >>= 1) sum += __shfl_xor_sync(~0u, sum, o);
    const float rinv = 1.0f / sum;

#pragma unroll
    for (int i = 0; i < 16; i++) {
        const int pi = i * 32 + lane;
        if (pi < plim) {
            float p0 = v[i].x * rinv, p1 = v[i].y * rinv;
            *(float2*)(arow + 2 * pi) = make_float2(p0, p1);
            srow[pi] = __floats2half2_rn(p0, p1);
        } else {
            *(float2*)(arow + 2 * pi) = make_float2(0.f, 0.f);
        }
    }
}

// ============================================================================
// Head mean over fp16 oh -> fp16 om. 2 elems (half2) per thread.
// oh index: h*1048576 + (b*1024+t)*128 + d  (element units).
// ============================================================================
__global__ __launch_bounds__(256)
void reduce_mean_h(const __half2* __restrict__ oh, __half2* __restrict__ om)
{
    const size_t i = (size_t)blockIdx.x * 256 + threadIdx.x;   // half2 units
    float sx = 0.f, sy = 0.f;
#pragma unroll
    for (int h = 0; h < NH; h++) {
        __half2 v = oh[(size_t)h * (MROWS * DK / 2) + i];
        sx += __low2float(v);
        sy += __high2float(v);
    }
    om[i] = __floats2half2_rn(sx * 0.125f, sy * 0.125f);
}

// ============================================================================
extern "C" void kernel_launch(void* const* d_in, const int* in_sizes, int n_in,
                              void* d_out, int out_size)
{
    const float* q  = (const float*)d_in[0];
    const float* k  = (const float*)d_in[1];
    const float* v  = (const float*)d_in[2];
    /* d_in[3] = mask: exact causal tril; handled analytically */
    const float* Wq = (const float*)d_in[4];
    const float* Wk = (const float*)d_in[5];
    const float* Wv = (const float*)d_in[6];
    const float* Wo = (const float*)d_in[7];

    float* out  = (float*)d_out;                       // (B,T,DM)
    float* attn = out + (size_t)MROWS * DM;            // (H,B,T,S)

    __half *q2,*k2,*v2,*wqh,*wkh,*wvh,*woh,*qh,*khh,*vth,*sc,*oh,*om;
    cudaGetSymbolAddress((void**)&q2,  g_q2);
    cudaGetSymbolAddress((void**)&k2,  g_k2);
    cudaGetSymbolAddress((void**)&v2,  g_v2);
    cudaGetSymbolAddress((void**)&wqh, g_wqh);
    cudaGetSymbolAddress((void**)&wkh, g_wkh);
    cudaGetSymbolAddress((void**)&wvh, g_wvh);
    cudaGetSymbolAddress((void**)&woh, g_woh);
    cudaGetSymbolAddress((void**)&qh,  g_qh);
    cudaGetSymbolAddress((void**)&khh, g_khh);
    cudaGetSymbolAddress((void**)&vth, g_vth);
    cudaGetSymbolAddress((void**)&sc,  g_sc);
    cudaGetSymbolAddress((void**)&oh,  g_oh);
    cudaGetSymbolAddress((void**)&om,  g_om);

    const int GSM = 3 * 2 * 16384;                     // 96 KB dynamic smem
    cudaFuncSetAttribute(gemm_t<0,0>, cudaFuncAttributeMaxDynamicSharedMemorySize, GSM);
    cudaFuncSetAttribute(gemm_t<0,1>, cudaFuncAttributeMaxDynamicSharedMemorySize, GSM);
    cudaFuncSetAttribute(gemm_t<0,2>, cudaFuncAttributeMaxDynamicSharedMemorySize, GSM);
    cudaFuncSetAttribute(gemm_t<1,1>, cudaFuncAttributeMaxDynamicSharedMemorySize, GSM);
    cudaFuncSetAttribute(gemm_t<2,1>, cudaFuncAttributeMaxDynamicSharedMemorySize, GSM);

    dim3 tb(32, 8);

    // ---- operand preparation ----
    conv_h3<<<dim3(MROWS * DM / 1024, 3), 256>>>(q, q2, k, k2, v, v2);
    transpose_w18<<<dim3(4, 32, 18), tb>>>(Wq, Wk, Wv, Wo, wqh, wkh, wvh, woh);

    // ---- projections ----
    gemm_t<0,1><<<dim3(8, 64, 1), 256, GSM>>>(q2, wqh, qh, 1.f,
                                              1024, 1024, 1024, 1024,
                                              0,0, 0,0, 0,0);
    gemm_t<0,1><<<dim3(8, 64, 1), 256, GSM>>>(k2, wkh, khh, 1.f,
                                              1024, 1024, 1024, 1024,
                                              0,0, 0,0, 0,0);
    gemm_t<0,2><<<dim3(1, 64, 1), 256, GSM>>>(v2, wvh, vth, 1.f,
                                              1024, 1024, 1024, 128,
                                              0,0, 0,0, 0,0);

    // ---- scores = qh @ kh^T -> fp16 sc (batched z = b*8+h, causal skip) ----
    gemm_t<1,1><<<dim3(8, 8, 64), 256, GSM>>>(qh, khh, sc, 1.f,
                                              128, 1024, 1024, 1024,
                                              1048576LL, 128LL,      // A: b, h
                                              1048576LL, 128LL,      // B: b, h
                                              1048576LL, 8388608LL); // C: b, h

    // ---- softmax: sc(fp16) -> attn(fp32) + P in-place into sc ----
    softmax_kernel<<<dim3(NH * BB * TT / 8), 256>>>(sc, attn);

    // ---- O_h = P @ V  (per-head, causal K limit; 512 CTAs; fp16 out) ----
    gemm_t<2,1><<<dim3(1, 8, 64), 256, GSM>>>(sc, vth, oh, 1.f,
                                              1024, 1024, 1024, 128,
                                              1048576LL, 8388608LL,  // A: b, h
                                              131072LL,  0LL,        // B: b
                                              131072LL,  1048576LL); // C: b, h

    // ---- head mean (fp16 in/out) ----
    reduce_mean_h<<<dim3((MROWS * DK / 2) / 256), 256>>>(
        (const __half2*)oh, (__half2*)om);

    // ---- out = Om @ Wo ----
    gemm_t<0,0><<<dim3(8, 64, 1), 256, GSM>>>(om, woh, out, 1.f,
                                              128, 128, 128, 1024,
                                              0,0, 0,0, 0,0);
}

// round 13
// speedup vs baseline: 1.1009x; 1.1009x over previous
#include <cuda_runtime.h>
#include <cuda_fp16.h>
#include <stdint.h>
#include <math.h>

#define BB 8
#define TT 1024
#define DM 1024
#define NH 8
#define DK 128
#define MROWS (BB*TT)   /* 8192 */

// ---------------- scratch (device globals; no cudaMalloc allowed) ----------
__device__ __half g_q2 [(size_t)MROWS * DM];        // 16 MB
__device__ __half g_k2 [(size_t)MROWS * DM];        // 16 MB
__device__ __half g_v2 [(size_t)MROWS * DM];        // 16 MB
__device__ __half g_wqh[(size_t)NH * DM * DK];      // 2 MB  [h][128][1024]
__device__ __half g_wkh[(size_t)NH * DM * DK];      // 2 MB
__device__ __half g_wvh[(size_t)DM * DK];           // [128][1024]
__device__ __half g_woh[(size_t)DM * DK];           // [1024][128]
__device__ __half g_qh [(size_t)MROWS * DM];        // 16 MB  qh (A of scores)
__device__ __half g_khh[(size_t)MROWS * DM];        // 16 MB  kh (B of scores)
__device__ __half g_vth[(size_t)MROWS * DK];        // 2 MB   vhT [b][128][1024]
__device__ __half g_sc [(size_t)NH * BB * TT * TT]; // 134 MB scores fp16 -> P in place
__device__ __half g_oh [(size_t)NH * MROWS * DK];   // 16 MB  per-head O (fp16)
__device__ __half g_om [(size_t)MROWS * DK];        // 2 MB   head-mean fp16

// ======================= helpers ==============================
__device__ __forceinline__ uint32_t smem_u32(const void* p) {
    uint32_t a;
    asm("{ .reg .u64 t; cvta.to.shared.u64 t, %1; cvt.u32.u64 %0, t; }"
        : "=r"(a) : "l"(p));
    return a;
}
__device__ __forceinline__ uint32_t sw128(uint32_t off) {
    return off ^ ((off >> 3) & 0x70);
}
__device__ __forceinline__ void ldm4(uint32_t* d, uint32_t addr) {
    asm volatile("ldmatrix.sync.aligned.m8n8.x4.shared.b16 {%0,%1,%2,%3}, [%4];"
                 : "=r"(d[0]), "=r"(d[1]), "=r"(d[2]), "=r"(d[3]) : "r"(addr));
}
__device__ __forceinline__ void mma16816(float* c, const uint32_t* a, const uint32_t* b) {
    asm volatile(
        "mma.sync.aligned.m16n8k16.row.col.f32.f16.f16.f32 "
        "{%0,%1,%2,%3}, {%4,%5,%6,%7}, {%8,%9}, {%0,%1,%2,%3};"
        : "+f"(c[0]), "+f"(c[1]), "+f"(c[2]), "+f"(c[3])
        : "r"(a[0]), "r"(a[1]), "r"(a[2]), "r"(a[3]), "r"(b[0]), "r"(b[1]));
}
#define CP16(sa, ga) \
    asm volatile("cp.async.ca.shared.global [%0], [%1], 16;" :: "r"(sa), "l"(ga))
#define CP_COMMIT() asm volatile("cp.async.commit_group;" ::: "memory")
#define CP_WAIT2()  asm volatile("cp.async.wait_group 2;"  ::: "memory")

// ============================================================================
// Templated fp16 HMMA GEMM:  D[128x128 tile] = A(MxK) * B(NxK)^T * cscale
// 3-stage cp.async pipeline (2x16KB per stage = 96KB smem, 2 CTAs/SM).
// MODE 0: plain.  MODE 1: causal score tile skip.  MODE 2: causal K-limit.
// OUT 0: fp32.  OUT 1: fp16.  OUT 2: fp16 transposed (vhT[b][n][t]).
// (Exact R9 mainloop — measured 62.7us / tensor 45% on the 8192x1024x1024.)
// ============================================================================
template<int MODE, int OUT>
__global__ __launch_bounds__(256, 2)
void gemm_t(const __half* __restrict__ Ah, const __half* __restrict__ Bh,
            void* __restrict__ Cout, float cscale,
            int K, int lda, int ldb, int ldc,
            long long aS1, long long aS2, long long bS1, long long bS2,
            long long cS1, long long cS2)
{
    extern __shared__ char sm[];
    const int tid  = threadIdx.x;
    const int wid  = tid >> 5;
    const int lane = tid & 31;
    const int row0 = blockIdx.y * 128;
    const int col0 = blockIdx.x * 128;
    if (MODE == 1 && col0 >= row0 + 128) return;     // fully above diagonal

    const int z1 = blockIdx.z >> 3, z2 = blockIdx.z & 7;
    const __half* Ab  = Ah + (size_t)z1 * aS1 + (size_t)z2 * aS2;
    const __half* Bhb = Bh + (size_t)z1 * bS1 + (size_t)z2 * bS2;

    const int Keff = (MODE == 2) ? (row0 + 128 < K ? row0 + 128 : K) : K;
    const int nCh  = Keff >> 6;                      // 64-wide K chunks (>=2)

    const uint32_t sb = smem_u32(sm);

#define FILL(cc) do {                                                         \
        uint32_t stb = sb + (uint32_t)((cc) % 3) * 32768;                     \
        const size_t k0 = (size_t)(cc) << 6;                                  \
        _Pragma("unroll")                                                     \
        for (int i = 0; i < 4; i++) {                                         \
            int id = tid + 256 * i;                                           \
            int rr = id >> 3, sg = id & 7;                                    \
            uint32_t sw = sw128((uint32_t)rr * 128 + sg * 16);                \
            CP16(stb + sw,         Ab  + (size_t)(row0 + rr) * lda + k0 + sg * 8); \
            CP16(stb + 16384 + sw, Bhb + (size_t)(col0 + rr) * ldb + k0 + sg * 8); \
        }                                                                     \
    } while (0)

    // ---- warp tiling: 2 (m) x 4 (n) warps; each 64 rows x 32 cols ----
    const int wm = (wid >> 2) * 64;
    const int wn = (wid & 3) * 32;

    uint32_t aBase[4], bBase[2];
#pragma unroll
    for (int mt = 0; mt < 4; mt++) {
        int r = wm + mt * 16 + ((lane >> 3) & 1) * 8 + (lane & 7);
        aBase[mt] = (uint32_t)r * 128 + (uint32_t)((lane >> 4) * 8) * 2;
    }
#pragma unroll
    for (int np = 0; np < 2; np++) {
        int r = wn + np * 16 + (lane >> 4) * 8 + (lane & 7);
        bBase[np] = (uint32_t)r * 128 + (uint32_t)(((lane >> 3) & 1) * 8) * 2;
    }

    float acc[4][4][4];
#pragma unroll
    for (int mt = 0; mt < 4; mt++)
#pragma unroll
        for (int nt = 0; nt < 4; nt++)
#pragma unroll
            for (int i = 0; i < 4; i++) acc[mt][nt][i] = 0.f;

    // ---- prologue: 3 stages in flight ----
#pragma unroll
    for (int p = 0; p < 3; p++) { if (p < nCh) FILL(p); CP_COMMIT(); }

    for (int c = 0; c < nCh; ++c) {
        CP_WAIT2();
        __syncthreads();
        const uint32_t tb = sb + (uint32_t)(c % 3) * 32768;
#pragma unroll
        for (int ks = 0; ks < 4; ks++) {
            const uint32_t kb2 = (uint32_t)ks * 32;
            uint32_t a[4][4], b2[2][4];
#pragma unroll
            for (int mt = 0; mt < 4; mt++)
                ldm4(a[mt], tb + sw128(aBase[mt] + kb2));
#pragma unroll
            for (int np = 0; np < 2; np++)
                ldm4(b2[np], tb + 16384 + sw128(bBase[np] + kb2));
#pragma unroll
            for (int mt = 0; mt < 4; mt++)
#pragma unroll
                for (int nt = 0; nt < 4; nt++)
                    mma16816(acc[mt][nt], a[mt], &b2[nt >> 1][(nt & 1) * 2]);
        }
        __syncthreads();                // all reads of buf (c%3) done
        int f = c + 3;
        if (f < nCh) FILL(f);
        CP_COMMIT();
    }
#undef FILL

    // ---- epilogue (single variant per instantiation) ----
#pragma unroll
    for (int mt = 0; mt < 4; mt++) {
        const int r = row0 + wm + mt * 16 + (lane >> 2);
#pragma unroll
        for (int nt = 0; nt < 4; nt++) {
            const int cc = col0 + wn + nt * 8 + (lane & 3) * 2;
            float a0 = acc[mt][nt][0], a1 = acc[mt][nt][1];
            float a2 = acc[mt][nt][2], a3 = acc[mt][nt][3];
            if (cscale != 1.f) { a0 *= cscale; a1 *= cscale; a2 *= cscale; a3 *= cscale; }
            if (OUT == 0) {
                float* Cb = (float*)Cout + (size_t)z1 * cS1 + (size_t)z2 * cS2;
                float* p = Cb + (size_t)r * ldc + cc;
                *(float2*)p = make_float2(a0, a1);
                *(float2*)(p + (size_t)8 * ldc) = make_float2(a2, a3);
            } else if (OUT == 1) {
                __half* Cb = (__half*)Cout + (size_t)z1 * cS1 + (size_t)z2 * cS2;
                *(__half2*)(Cb + (size_t)r * ldc + cc) = __floats2half2_rn(a0, a1);
                *(__half2*)(Cb + (size_t)(r + 8) * ldc + cc) = __floats2half2_rn(a2, a3);
            } else {   // vhT[b][n][t]: b = r>>10, t = r&1023
                __half* CT = (__half*)Cout;
                size_t b0 = (size_t)(r >> 10) * 131072 + (r & 1023);
                CT[b0 + (size_t)cc * 1024]       = __float2half_rn(a0);
                CT[b0 + (size_t)(cc + 1) * 1024] = __float2half_rn(a1);
                size_t b1 = (size_t)((r + 8) >> 10) * 131072 + ((r + 8) & 1023);
                CT[b1 + (size_t)cc * 1024]       = __float2half_rn(a2);
                CT[b1 + (size_t)(cc + 1) * 1024] = __float2half_rn(a3);
            }
        }
    }
}

// ============================================================================
// fp32 -> fp16 convert; blockIdx.y selects one of 3 (in,out) pairs
// ============================================================================
__global__ __launch_bounds__(256)
void conv_h3(const float* __restrict__ i0, __half* __restrict__ o0,
             const float* __restrict__ i1, __half* __restrict__ o1,
             const float* __restrict__ i2, __half* __restrict__ o2)
{
    const float* in  = blockIdx.y == 0 ? i0 : (blockIdx.y == 1 ? i1 : i2);
    __half*      out = blockIdx.y == 0 ? o0 : (blockIdx.y == 1 ? o1 : o2);
    const size_t i = ((size_t)blockIdx.x * 256 + threadIdx.x) * 4;
    float4 v = *(const float4*)(in + i);
    *(__half2*)(out + i)     = __floats2half2_rn(v.x, v.y);
    *(__half2*)(out + i + 2) = __floats2half2_rn(v.z, v.w);
}

// ============================================================================
// Merged weight transpose: z<8 Wq[z], z<16 Wk[z-8], z==16 Wv (all 1024x128),
// z==17 Wo (128x1024, block indices swapped).
// ============================================================================
__global__ __launch_bounds__(256)
void transpose_w18(const float* __restrict__ Wq, const float* __restrict__ Wk,
                   const float* __restrict__ Wv, const float* __restrict__ Wo,
                   __half* __restrict__ wqh, __half* __restrict__ wkh,
                   __half* __restrict__ wvh, __half* __restrict__ woh)
{
    __shared__ float t[32][33];
    const int z = blockIdx.z;
    const float* in; __half* out;
    int R, C, r0, c0;
    if (z < 8)       { in = Wq + (size_t)z * 131072;       out = wqh + (size_t)z * 131072;
                       R = 1024; C = 128; r0 = blockIdx.y * 32; c0 = blockIdx.x * 32; }
    else if (z < 16) { in = Wk + (size_t)(z - 8) * 131072; out = wkh + (size_t)(z - 8) * 131072;
                       R = 1024; C = 128; r0 = blockIdx.y * 32; c0 = blockIdx.x * 32; }
    else if (z == 16){ in = Wv;                            out = wvh;
                       R = 1024; C = 128; r0 = blockIdx.y * 32; c0 = blockIdx.x * 32; }
    else             { in = Wo;                            out = woh;
                       R = 128;  C = 1024; r0 = blockIdx.x * 32; c0 = blockIdx.y * 32; }
    const int tx = threadIdx.x, ty = threadIdx.y;
#pragma unroll
    for (int i = 0; i < 32; i += 8)
        t[ty + i][tx] = in[(size_t)(r0 + ty + i) * C + c0 + tx];
    __syncthreads();
#pragma unroll
    for (int i = 0; i < 32; i += 8)
        out[(size_t)(c0 + ty + i) * R + r0 + tx] = __float2half_rn(t[tx][ty + i]);
}

// ============================================================================
// Causal softmax (R9 structure — UNCONDITIONAL batched row reads, MLP=16):
// reads full fp16 score row from sc, writes full fp32 attn row (zeros above
// diagonal) and fp16 P in-place into sc up to the causal 128-block edge.
// One warp per row.
// ============================================================================
__global__ __launch_bounds__(256)
void softmax_kernel(__half* __restrict__ sc, float* __restrict__ attn)
{
    const int gw   = blockIdx.x * 8 + (threadIdx.x >> 5);
    const int lane = threadIdx.x & 31;
    const int t    = gw & (TT - 1);
    __half2* srow = (__half2*)(sc + (size_t)gw * TT);
    float*   arow = attn + (size_t)gw * TT;

    float2 v[16];
    float m = -1e30f;
#pragma unroll
    for (int i = 0; i < 16; i++) {
        const int pi = i * 32 + lane;          // half2 index; s = 2*pi, 2*pi+1
        __half2 h = srow[pi];
        v[i].x = (2 * pi     <= t) ? __low2float(h)  : -1e30f;
        v[i].y = (2 * pi + 1 <= t) ? __high2float(h) : -1e30f;
        m = fmaxf(m, fmaxf(v[i].x, v[i].y));
    }
#pragma unroll
    for (int o = 16; o; o >>= 1) m = fmaxf(m, __shfl_xor_sync(~0u, m, o));

    const float scale = 0.08838834764831845f;   // 1/sqrt(128)
    float sum = 0.f;
#pragma unroll
    for (int i = 0; i < 16; i++) {
        const int pi = i * 32 + lane;
        float e0 = (2 * pi     <= t) ? __expf((v[i].x - m) * scale) : 0.f;
        float e1 = (2 * pi + 1 <= t) ? __expf((v[i].y - m) * scale) : 0.f;
        v[i].x = e0; v[i].y = e1;
        sum += e0 + e1;
    }
#pragma unroll
    for (int o = 16; o; o >>= 1) sum += __shfl_xor_sync(~0u, sum, o);
    const float rinv = 1.0f / sum;

    const int plim = (((t >> 7) + 1) << 6);     // half2 units PV will read
#pragma unroll
    for (int i = 0; i < 16; i++) {
        const int pi = i * 32 + lane;
        float p0 = v[i].x * rinv, p1 = v[i].y * rinv;
        *(float2*)(arow + 2 * pi) = make_float2(p0, p1);
        if (pi < plim) srow[pi] = __floats2half2_rn(p0, p1);
    }
}

// ============================================================================
// Head mean over fp16 oh -> fp16 om. 2 elems (half2) per thread.
// ============================================================================
__global__ __launch_bounds__(256)
void reduce_mean_h(const __half2* __restrict__ oh, __half2* __restrict__ om)
{
    const size_t i = (size_t)blockIdx.x * 256 + threadIdx.x;   // half2 units
    float sx = 0.f, sy = 0.f;
#pragma unroll
    for (int h = 0; h < NH; h++) {
        __half2 v = oh[(size_t)h * (MROWS * DK / 2) + i];
        sx += __low2float(v);
        sy += __high2float(v);
    }
    om[i] = __floats2half2_rn(sx * 0.125f, sy * 0.125f);
}

// ============================================================================
extern "C" void kernel_launch(void* const* d_in, const int* in_sizes, int n_in,
                              void* d_out, int out_size)
{
    const float* q  = (const float*)d_in[0];
    const float* k  = (const float*)d_in[1];
    const float* v  = (const float*)d_in[2];
    /* d_in[3] = mask: exact causal tril; handled analytically */
    const float* Wq = (const float*)d_in[4];
    const float* Wk = (const float*)d_in[5];
    const float* Wv = (const float*)d_in[6];
    const float* Wo = (const float*)d_in[7];

    float* out  = (float*)d_out;                       // (B,T,DM)
    float* attn = out + (size_t)MROWS * DM;            // (H,B,T,S)

    __half *q2,*k2,*v2,*wqh,*wkh,*wvh,*woh,*qh,*khh,*vth,*sc,*oh,*om;
    cudaGetSymbolAddress((void**)&q2,  g_q2);
    cudaGetSymbolAddress((void**)&k2,  g_k2);
    cudaGetSymbolAddress((void**)&v2,  g_v2);
    cudaGetSymbolAddress((void**)&wqh, g_wqh);
    cudaGetSymbolAddress((void**)&wkh, g_wkh);
    cudaGetSymbolAddress((void**)&wvh, g_wvh);
    cudaGetSymbolAddress((void**)&woh, g_woh);
    cudaGetSymbolAddress((void**)&qh,  g_qh);
    cudaGetSymbolAddress((void**)&khh, g_khh);
    cudaGetSymbolAddress((void**)&vth, g_vth);
    cudaGetSymbolAddress((void**)&sc,  g_sc);
    cudaGetSymbolAddress((void**)&oh,  g_oh);
    cudaGetSymbolAddress((void**)&om,  g_om);

    const int GSM = 3 * 2 * 16384;                     // 96 KB dynamic smem
    cudaFuncSetAttribute(gemm_t<0,0>, cudaFuncAttributeMaxDynamicSharedMemorySize, GSM);
    cudaFuncSetAttribute(gemm_t<0,1>, cudaFuncAttributeMaxDynamicSharedMemorySize, GSM);
    cudaFuncSetAttribute(gemm_t<0,2>, cudaFuncAttributeMaxDynamicSharedMemorySize, GSM);
    cudaFuncSetAttribute(gemm_t<1,1>, cudaFuncAttributeMaxDynamicSharedMemorySize, GSM);
    cudaFuncSetAttribute(gemm_t<2,1>, cudaFuncAttributeMaxDynamicSharedMemorySize, GSM);

    dim3 tb(32, 8);

    // ---- operand preparation ----
    conv_h3<<<dim3(MROWS * DM / 1024, 3), 256>>>(q, q2, k, k2, v, v2);
    transpose_w18<<<dim3(4, 32, 18), tb>>>(Wq, Wk, Wv, Wo, wqh, wkh, wvh, woh);

    // ---- projections ----
    gemm_t<0,1><<<dim3(8, 64, 1), 256, GSM>>>(q2, wqh, qh, 1.f,
                                              1024, 1024, 1024, 1024,
                                              0,0, 0,0, 0,0);
    gemm_t<0,1><<<dim3(8, 64, 1), 256, GSM>>>(k2, wkh, khh, 1.f,
                                              1024, 1024, 1024, 1024,
                                              0,0, 0,0, 0,0);
    gemm_t<0,2><<<dim3(1, 64, 1), 256, GSM>>>(v2, wvh, vth, 1.f,
                                              1024, 1024, 1024, 128,
                                              0,0, 0,0, 0,0);

    // ---- scores = qh @ kh^T -> fp16 sc (batched z = b*8+h, causal skip) ----
    gemm_t<1,1><<<dim3(8, 8, 64), 256, GSM>>>(qh, khh, sc, 1.f,
                                              128, 1024, 1024, 1024,
                                              1048576LL, 128LL,      // A: b, h
                                              1048576LL, 128LL,      // B: b, h
                                              1048576LL, 8388608LL); // C: b, h

    // ---- softmax: sc(fp16) -> attn(fp32) + P in-place into sc ----
    softmax_kernel<<<dim3(NH * BB * TT / 8), 256>>>(sc, attn);

    // ---- O_h = P @ V  (per-head, causal K limit; 512 CTAs; fp16 out) ----
    gemm_t<2,1><<<dim3(1, 8, 64), 256, GSM>>>(sc, vth, oh, 1.f,
                                              1024, 1024, 1024, 128,
                                              1048576LL, 8388608LL,  // A: b, h
                                              131072LL,  0LL,        // B: b
                                              131072LL,  1048576LL); // C: b, h

    // ---- head mean (fp16 in/out) ----
    reduce_mean_h<<<dim3((MROWS * DK / 2) / 256), 256>>>(
        (const __half2*)oh, (__half2*)om);

    // ---- out = Om @ Wo ----
    gemm_t<0,0><<<dim3(8, 64, 1), 256, GSM>>>(om, woh, out, 1.f,
                                              128, 128, 128, 1024,
                                              0,0, 0,0, 0,0);
}

// round 14
// speedup vs baseline: 1.1136x; 1.0115x over previous
#include <cuda_runtime.h>
#include <cuda_fp16.h>
#include <stdint.h>
#include <math.h>

#define BB 8
#define TT 1024
#define DM 1024
#define NH 8
#define DK 128
#define MROWS (BB*TT)   /* 8192 */

// ---------------- scratch (device globals; no cudaMalloc allowed) ----------
__device__ __half g_q2 [(size_t)MROWS * DM];        // 16 MB
__device__ __half g_k2 [(size_t)MROWS * DM];        // 16 MB
__device__ __half g_v2 [(size_t)MROWS * DM];        // 16 MB
__device__ __half g_wqh[(size_t)NH * DM * DK];      // 2 MB  [h][128][1024]
__device__ __half g_wkh[(size_t)NH * DM * DK];      // 2 MB
__device__ __half g_wvh[(size_t)DM * DK];           // [128][1024]
__device__ __half g_woh[(size_t)DM * DK];           // [1024][128]
__device__ __half g_qh [(size_t)MROWS * DM];        // 16 MB  qh (A of scores)
__device__ __half g_khh[(size_t)MROWS * DM];        // 16 MB  kh (B of scores)
__device__ __half g_vth[(size_t)MROWS * DK];        // 2 MB   vhT [b][128][1024]
__device__ __half g_sc [(size_t)NH * BB * TT * TT]; // 134 MB scores fp16 -> P in place
__device__ __half g_oh [(size_t)NH * MROWS * DK];   // 16 MB  per-head O (fp16)
__device__ __half g_om [(size_t)MROWS * DK];        // 2 MB   head-mean fp16

// ======================= helpers ==============================
__device__ __forceinline__ uint32_t smem_u32(const void* p) {
    uint32_t a;
    asm("{ .reg .u64 t; cvta.to.shared.u64 t, %1; cvt.u32.u64 %0, t; }"
        : "=r"(a) : "l"(p));
    return a;
}
__device__ __forceinline__ uint32_t sw128(uint32_t off) {
    return off ^ ((off >> 3) & 0x70);
}
__device__ __forceinline__ void ldm4(uint32_t* d, uint32_t addr) {
    asm volatile("ldmatrix.sync.aligned.m8n8.x4.shared.b16 {%0,%1,%2,%3}, [%4];"
                 : "=r"(d[0]), "=r"(d[1]), "=r"(d[2]), "=r"(d[3]) : "r"(addr));
}
__device__ __forceinline__ void mma16816(float* c, const uint32_t* a, const uint32_t* b) {
    asm volatile(
        "mma.sync.aligned.m16n8k16.row.col.f32.f16.f16.f32 "
        "{%0,%1,%2,%3}, {%4,%5,%6,%7}, {%8,%9}, {%0,%1,%2,%3};"
        : "+f"(c[0]), "+f"(c[1]), "+f"(c[2]), "+f"(c[3])
        : "r"(a[0]), "r"(a[1]), "r"(a[2]), "r"(a[3]), "r"(b[0]), "r"(b[1]));
}
#define CP16(sa, ga) \
    asm volatile("cp.async.ca.shared.global [%0], [%1], 16;" :: "r"(sa), "l"(ga))
#define CP_COMMIT() asm volatile("cp.async.commit_group;" ::: "memory")
#define CP_WAIT2()  asm volatile("cp.async.wait_group 2;"  ::: "memory")

// ============================================================================
// Templated fp16 HMMA GEMM:  D[128x128 tile] = A(MxK) * B(NxK)^T * cscale
// 3-stage cp.async pipeline (2x16KB per stage = 96KB smem, 2 CTAs/SM).
// MODE 0: plain.  MODE 1: causal score tile skip — dead tiles write their
//         fp32 zero attn tile to Zattn (same z strides as C) then exit.
// MODE 2: causal K-limit.
// OUT 0: fp32.  OUT 1: fp16.  OUT 2: fp16 transposed (vhT[b][n][t]).
// (R9 mainloop — measured 62.7us / tensor 45% on the 8192x1024x1024.)
// ============================================================================
template<int MODE, int OUT>
__global__ __launch_bounds__(256, 2)
void gemm_t(const __half* __restrict__ Ah, const __half* __restrict__ Bh,
            void* __restrict__ Cout, float* __restrict__ Zattn, float cscale,
            int K, int lda, int ldb, int ldc,
            long long aS1, long long aS2, long long bS1, long long bS2,
            long long cS1, long long cS2)
{
    extern __shared__ char sm[];
    const int tid  = threadIdx.x;
    const int wid  = tid >> 5;
    const int lane = tid & 31;
    const int row0 = blockIdx.y * 128;
    const int col0 = blockIdx.x * 128;
    const int z1 = blockIdx.z >> 3, z2 = blockIdx.z & 7;

    if (MODE == 1 && col0 >= row0 + 128) {
        // fully above diagonal: attn is exactly zero here — write it now
        // (rides free under this launch's 3.8%-busy DRAM).
        float* Zb = Zattn + (size_t)z1 * cS1 + (size_t)z2 * cS2
                  + (size_t)row0 * ldc + col0;
        const float4 z4 = make_float4(0.f, 0.f, 0.f, 0.f);
#pragma unroll
        for (int i = 0; i < 16; i++) {
            int id = tid + 256 * i;
            int rr = id >> 5, ccc = (id & 31) * 4;
            *(float4*)(Zb + (size_t)rr * ldc + ccc) = z4;
        }
        return;
    }

    const __half* Ab  = Ah + (size_t)z1 * aS1 + (size_t)z2 * aS2;
    const __half* Bhb = Bh + (size_t)z1 * bS1 + (size_t)z2 * bS2;

    const int Keff = (MODE == 2) ? (row0 + 128 < K ? row0 + 128 : K) : K;
    const int nCh  = Keff >> 6;                      // 64-wide K chunks (>=2)

    const uint32_t sb = smem_u32(sm);

#define FILL(cc) do {                                                         \
        uint32_t stb = sb + (uint32_t)((cc) % 3) * 32768;                     \
        const size_t k0 = (size_t)(cc) << 6;                                  \
        _Pragma("unroll")                                                     \
        for (int i = 0; i < 4; i++) {                                         \
            int id = tid + 256 * i;                                           \
            int rr = id >> 3, sg = id & 7;                                    \
            uint32_t sw = sw128((uint32_t)rr * 128 + sg * 16);                \
            CP16(stb + sw,         Ab  + (size_t)(row0 + rr) * lda + k0 + sg * 8); \
            CP16(stb + 16384 + sw, Bhb + (size_t)(col0 + rr) * ldb + k0 + sg * 8); \
        }                                                                     \
    } while (0)

    // ---- warp tiling: 2 (m) x 4 (n) warps; each 64 rows x 32 cols ----
    const int wm = (wid >> 2) * 64;
    const int wn = (wid & 3) * 32;

    uint32_t aBase[4], bBase[2];
#pragma unroll
    for (int mt = 0; mt < 4; mt++) {
        int r = wm + mt * 16 + ((lane >> 3) & 1) * 8 + (lane & 7);
        aBase[mt] = (uint32_t)r * 128 + (uint32_t)((lane >> 4) * 8) * 2;
    }
#pragma unroll
    for (int np = 0; np < 2; np++) {
        int r = wn + np * 16 + (lane >> 4) * 8 + (lane & 7);
        bBase[np] = (uint32_t)r * 128 + (uint32_t)(((lane >> 3) & 1) * 8) * 2;
    }

    float acc[4][4][4];
#pragma unroll
    for (int mt = 0; mt < 4; mt++)
#pragma unroll
        for (int nt = 0; nt < 4; nt++)
#pragma unroll
            for (int i = 0; i < 4; i++) acc[mt][nt][i] = 0.f;

    // ---- prologue: 3 stages in flight ----
#pragma unroll
    for (int p = 0; p < 3; p++) { if (p < nCh) FILL(p); CP_COMMIT(); }

    for (int c = 0; c < nCh; ++c) {
        CP_WAIT2();
        __syncthreads();
        const uint32_t tb = sb + (uint32_t)(c % 3) * 32768;
#pragma unroll
        for (int ks = 0; ks < 4; ks++) {
            const uint32_t kb2 = (uint32_t)ks * 32;
            uint32_t a[4][4], b2[2][4];
#pragma unroll
            for (int mt = 0; mt < 4; mt++)
                ldm4(a[mt], tb + sw128(aBase[mt] + kb2));
#pragma unroll
            for (int np = 0; np < 2; np++)
                ldm4(b2[np], tb + 16384 + sw128(bBase[np] + kb2));
#pragma unroll
            for (int mt = 0; mt < 4; mt++)
#pragma unroll
                for (int nt = 0; nt < 4; nt++)
                    mma16816(acc[mt][nt], a[mt], &b2[nt >> 1][(nt & 1) * 2]);
        }
        __syncthreads();                // all reads of buf (c%3) done
        int f = c + 3;
        if (f < nCh) FILL(f);
        CP_COMMIT();
    }
#undef FILL

    // ---- epilogue (single variant per instantiation) ----
#pragma unroll
    for (int mt = 0; mt < 4; mt++) {
        const int r = row0 + wm + mt * 16 + (lane >> 2);
#pragma unroll
        for (int nt = 0; nt < 4; nt++) {
            const int cc = col0 + wn + nt * 8 + (lane & 3) * 2;
            float a0 = acc[mt][nt][0], a1 = acc[mt][nt][1];
            float a2 = acc[mt][nt][2], a3 = acc[mt][nt][3];
            if (cscale != 1.f) { a0 *= cscale; a1 *= cscale; a2 *= cscale; a3 *= cscale; }
            if (OUT == 0) {
                float* Cb = (float*)Cout + (size_t)z1 * cS1 + (size_t)z2 * cS2;
                float* p = Cb + (size_t)r * ldc + cc;
                *(float2*)p = make_float2(a0, a1);
                *(float2*)(p + (size_t)8 * ldc) = make_float2(a2, a3);
            } else if (OUT == 1) {
                __half* Cb = (__half*)Cout + (size_t)z1 * cS1 + (size_t)z2 * cS2;
                *(__half2*)(Cb + (size_t)r * ldc + cc) = __floats2half2_rn(a0, a1);
                *(__half2*)(Cb + (size_t)(r + 8) * ldc + cc) = __floats2half2_rn(a2, a3);
            } else {   // vhT[b][n][t]: b = r>>10, t = r&1023
                __half* CT = (__half*)Cout;
                size_t b0 = (size_t)(r >> 10) * 131072 + (r & 1023);
                CT[b0 + (size_t)cc * 1024]       = __float2half_rn(a0);
                CT[b0 + (size_t)(cc + 1) * 1024] = __float2half_rn(a1);
                size_t b1 = (size_t)((r + 8) >> 10) * 131072 + ((r + 8) & 1023);
                CT[b1 + (size_t)cc * 1024]       = __float2half_rn(a2);
                CT[b1 + (size_t)(cc + 1) * 1024] = __float2half_rn(a3);
            }
        }
    }
}

// ============================================================================
// fp32 -> fp16 convert; blockIdx.y selects one of 3 (in,out) pairs
// ============================================================================
__global__ __launch_bounds__(256)
void conv_h3(const float* __restrict__ i0, __half* __restrict__ o0,
             const float* __restrict__ i1, __half* __restrict__ o1,
             const float* __restrict__ i2, __half* __restrict__ o2)
{
    const float* in  = blockIdx.y == 0 ? i0 : (blockIdx.y == 1 ? i1 : i2);
    __half*      out = blockIdx.y == 0 ? o0 : (blockIdx.y == 1 ? o1 : o2);
    const size_t i = ((size_t)blockIdx.x * 256 + threadIdx.x) * 4;
    float4 v = *(const float4*)(in + i);
    *(__half2*)(out + i)     = __floats2half2_rn(v.x, v.y);
    *(__half2*)(out + i + 2) = __floats2half2_rn(v.z, v.w);
}

// ============================================================================
// Merged weight transpose: z<8 Wq[z], z<16 Wk[z-8], z==16 Wv (all 1024x128),
// z==17 Wo (128x1024, block indices swapped).
// ============================================================================
__global__ __launch_bounds__(256)
void transpose_w18(const float* __restrict__ Wq, const float* __restrict__ Wk,
                   const float* __restrict__ Wv, const float* __restrict__ Wo,
                   __half* __restrict__ wqh, __half* __restrict__ wkh,
                   __half* __restrict__ wvh, __half* __restrict__ woh)
{
    __shared__ float t[32][33];
    const int z = blockIdx.z;
    const float* in; __half* out;
    int R, C, r0, c0;
    if (z < 8)       { in = Wq + (size_t)z * 131072;       out = wqh + (size_t)z * 131072;
                       R = 1024; C = 128; r0 = blockIdx.y * 32; c0 = blockIdx.x * 32; }
    else if (z < 16) { in = Wk + (size_t)(z - 8) * 131072; out = wkh + (size_t)(z - 8) * 131072;
                       R = 1024; C = 128; r0 = blockIdx.y * 32; c0 = blockIdx.x * 32; }
    else if (z == 16){ in = Wv;                            out = wvh;
                       R = 1024; C = 128; r0 = blockIdx.y * 32; c0 = blockIdx.x * 32; }
    else             { in = Wo;                            out = woh;
                       R = 128;  C = 1024; r0 = blockIdx.x * 32; c0 = blockIdx.y * 32; }
    const int tx = threadIdx.x, ty = threadIdx.y;
#pragma unroll
    for (int i = 0; i < 32; i += 8)
        t[ty + i][tx] = in[(size_t)(r0 + ty + i) * C + c0 + tx];
    __syncthreads();
#pragma unroll
    for (int i = 0; i < 32; i += 8)
        out[(size_t)(c0 + ty + i) * R + r0 + tx] = __float2half_rn(t[tx][ty + i]);
}

// ============================================================================
// Causal softmax (UNCONDITIONAL batched row reads, MLP=16 — do not guard the
// loads; guarded loads cost ~33us, see R10/R12). Writes fp32 attn and fp16 P
// in-place into sc ONLY up to the causal 128-block edge (predicated stores —
// measured free). Zeros above the edge are written by the scores GEMM's dead
// tiles. One warp per row.
// ============================================================================
__global__ __launch_bounds__(256)
void softmax_kernel(__half* __restrict__ sc, float* __restrict__ attn)
{
    const int gw   = blockIdx.x * 8 + (threadIdx.x >> 5);
    const int lane = threadIdx.x & 31;
    const int t    = gw & (TT - 1);
    __half2* srow = (__half2*)(sc + (size_t)gw * TT);
    float*   arow = attn + (size_t)gw * TT;

    float2 v[16];
    float m = -1e30f;
#pragma unroll
    for (int i = 0; i < 16; i++) {
        const int pi = i * 32 + lane;          // half2 index; s = 2*pi, 2*pi+1
        __half2 h = srow[pi];
        v[i].x = (2 * pi     <= t) ? __low2float(h)  : -1e30f;
        v[i].y = (2 * pi + 1 <= t) ? __high2float(h) : -1e30f;
        m = fmaxf(m, fmaxf(v[i].x, v[i].y));
    }
#pragma unroll
    for (int o = 16; o; o >>= 1) m = fmaxf(m, __shfl_xor_sync(~0u, m, o));

    const float scale = 0.08838834764831845f;   // 1/sqrt(128)
    float sum = 0.f;
#pragma unroll
    for (int i = 0; i < 16; i++) {
        const int pi = i * 32 + lane;
        float e0 = (2 * pi     <= t) ? __expf((v[i].x - m) * scale) : 0.f;
        float e1 = (2 * pi + 1 <= t) ? __expf((v[i].y - m) * scale) : 0.f;
        v[i].x = e0; v[i].y = e1;
        sum += e0 + e1;
    }
#pragma unroll
    for (int o = 16; o; o >>= 1) sum += __shfl_xor_sync(~0u, sum, o);
    const float rinv = 1.0f / sum;

    const int plim = (((t >> 7) + 1) << 6);     // half2 units inside causal blocks
#pragma unroll
    for (int i = 0; i < 16; i++) {
        const int pi = i * 32 + lane;
        if (pi < plim) {
            float p0 = v[i].x * rinv, p1 = v[i].y * rinv;
            *(float2*)(arow + 2 * pi) = make_float2(p0, p1);
            srow[pi] = __floats2half2_rn(p0, p1);
        }
    }
}

// ============================================================================
// Head mean over fp16 oh -> fp16 om. 2 elems (half2) per thread.
// ============================================================================
__global__ __launch_bounds__(256)
void reduce_mean_h(const __half2* __restrict__ oh, __half2* __restrict__ om)
{
    const size_t i = (size_t)blockIdx.x * 256 + threadIdx.x;   // half2 units
    float sx = 0.f, sy = 0.f;
#pragma unroll
    for (int h = 0; h < NH; h++) {
        __half2 v = oh[(size_t)h * (MROWS * DK / 2) + i];
        sx += __low2float(v);
        sy += __high2float(v);
    }
    om[i] = __floats2half2_rn(sx * 0.125f, sy * 0.125f);
}

// ============================================================================
extern "C" void kernel_launch(void* const* d_in, const int* in_sizes, int n_in,
                              void* d_out, int out_size)
{
    const float* q  = (const float*)d_in[0];
    const float* k  = (const float*)d_in[1];
    const float* v  = (const float*)d_in[2];
    /* d_in[3] = mask: exact causal tril; handled analytically */
    const float* Wq = (const float*)d_in[4];
    const float* Wk = (const float*)d_in[5];
    const float* Wv = (const float*)d_in[6];
    const float* Wo = (const float*)d_in[7];

    float* out  = (float*)d_out;                       // (B,T,DM)
    float* attn = out + (size_t)MROWS * DM;            // (H,B,T,S)

    __half *q2,*k2,*v2,*wqh,*wkh,*wvh,*woh,*qh,*khh,*vth,*sc,*oh,*om;
    cudaGetSymbolAddress((void**)&q2,  g_q2);
    cudaGetSymbolAddress((void**)&k2,  g_k2);
    cudaGetSymbolAddress((void**)&v2,  g_v2);
    cudaGetSymbolAddress((void**)&wqh, g_wqh);
    cudaGetSymbolAddress((void**)&wkh, g_wkh);
    cudaGetSymbolAddress((void**)&wvh, g_wvh);
    cudaGetSymbolAddress((void**)&woh, g_woh);
    cudaGetSymbolAddress((void**)&qh,  g_qh);
    cudaGetSymbolAddress((void**)&khh, g_khh);
    cudaGetSymbolAddress((void**)&vth, g_vth);
    cudaGetSymbolAddress((void**)&sc,  g_sc);
    cudaGetSymbolAddress((void**)&oh,  g_oh);
    cudaGetSymbolAddress((void**)&om,  g_om);

    const int GSM = 3 * 2 * 16384;                     // 96 KB dynamic smem
    cudaFuncSetAttribute(gemm_t<0,0>, cudaFuncAttributeMaxDynamicSharedMemorySize, GSM);
    cudaFuncSetAttribute(gemm_t<0,1>, cudaFuncAttributeMaxDynamicSharedMemorySize, GSM);
    cudaFuncSetAttribute(gemm_t<0,2>, cudaFuncAttributeMaxDynamicSharedMemorySize, GSM);
    cudaFuncSetAttribute(gemm_t<1,1>, cudaFuncAttributeMaxDynamicSharedMemorySize, GSM);
    cudaFuncSetAttribute(gemm_t<2,1>, cudaFuncAttributeMaxDynamicSharedMemorySize, GSM);

    dim3 tb(32, 8);

    // ---- operand preparation ----
    conv_h3<<<dim3(MROWS * DM / 1024, 3), 256>>>(q, q2, k, k2, v, v2);
    transpose_w18<<<dim3(4, 32, 18), tb>>>(Wq, Wk, Wv, Wo, wqh, wkh, wvh, woh);

    // ---- projections ----
    gemm_t<0,1><<<dim3(8, 64, 1), 256, GSM>>>(q2, wqh, qh, nullptr, 1.f,
                                              1024, 1024, 1024, 1024,
                                              0,0, 0,0, 0,0);
    gemm_t<0,1><<<dim3(8, 64, 1), 256, GSM>>>(k2, wkh, khh, nullptr, 1.f,
                                              1024, 1024, 1024, 1024,
                                              0,0, 0,0, 0,0);
    gemm_t<0,2><<<dim3(1, 64, 1), 256, GSM>>>(v2, wvh, vth, nullptr, 1.f,
                                              1024, 1024, 1024, 128,
                                              0,0, 0,0, 0,0);

    // ---- scores = qh @ kh^T -> fp16 sc; dead tiles zero-fill attn ----
    gemm_t<1,1><<<dim3(8, 8, 64), 256, GSM>>>(qh, khh, sc, attn, 1.f,
                                              128, 1024, 1024, 1024,
                                              1048576LL, 128LL,      // A: b, h
                                              1048576LL, 128LL,      // B: b, h
                                              1048576LL, 8388608LL); // C: b, h

    // ---- softmax: sc(fp16) -> attn(fp32, causal range) + P into sc ----
    softmax_kernel<<<dim3(NH * BB * TT / 8), 256>>>(sc, attn);

    // ---- O_h = P @ V  (per-head, causal K limit; 512 CTAs; fp16 out) ----
    gemm_t<2,1><<<dim3(1, 8, 64), 256, GSM>>>(sc, vth, oh, nullptr, 1.f,
                                              1024, 1024, 1024, 128,
                                              1048576LL, 8388608LL,  // A: b, h
                                              131072LL,  0LL,        // B: b
                                              131072LL,  1048576LL); // C: b, h

    // ---- head mean (fp16 in/out) ----
    reduce_mean_h<<<dim3((MROWS * DK / 2) / 256), 256>>>(
        (const __half2*)oh, (__half2*)om);

    // ---- out = Om @ Wo ----
    gemm_t<0,0><<<dim3(8, 64, 1), 256, GSM>>>(om, woh, out, nullptr, 1.f,
                                              128, 128, 128, 1024,
                                              0,0, 0,0, 0,0);
}

// round 15
// speedup vs baseline: 1.1165x; 1.0026x over previous
#include <cuda_runtime.h>
#include <cuda_fp16.h>
#include <stdint.h>
#include <math.h>

#define BB 8
#define TT 1024
#define DM 1024
#define NH 8
#define DK 128
#define MROWS (BB*TT)   /* 8192 */

// ---------------- scratch (device globals; no cudaMalloc allowed) ----------
__device__ __half g_q2 [(size_t)MROWS * DM];        // 16 MB
__device__ __half g_k2 [(size_t)MROWS * DM];        // 16 MB
__device__ __half g_v2 [(size_t)MROWS * DM];        // 16 MB
__device__ __half g_wqh[(size_t)NH * DM * DK];      // 2 MB  [h][128][1024]
__device__ __half g_wkh[(size_t)NH * DM * DK];      // 2 MB
__device__ __half g_wvh[(size_t)DM * DK];           // [128][1024]
__device__ __half g_woh[(size_t)DM * DK];           // [1024][128]
__device__ __half g_qh [(size_t)MROWS * DM];        // 16 MB  qh (A of scores)
__device__ __half g_khh[(size_t)MROWS * DM];        // 16 MB  kh (B of scores)
__device__ __half g_vtp[(size_t)4 * MROWS * DK];    // 8 MB   vhT split-K partials
__device__ __half g_vth[(size_t)MROWS * DK];        // 2 MB   vhT [b][128][1024]
__device__ __half g_sc [(size_t)NH * BB * TT * TT]; // 134 MB scores fp16 -> P in place
__device__ __half g_oh [(size_t)NH * MROWS * DK];   // 16 MB  per-head O (fp16)
__device__ __half g_om [(size_t)MROWS * DK];        // 2 MB   head-mean fp16

// ======================= helpers ==============================
__device__ __forceinline__ uint32_t smem_u32(const void* p) {
    uint32_t a;
    asm("{ .reg .u64 t; cvta.to.shared.u64 t, %1; cvt.u32.u64 %0, t; }"
        : "=r"(a) : "l"(p));
    return a;
}
__device__ __forceinline__ uint32_t sw128(uint32_t off) {
    return off ^ ((off >> 3) & 0x70);
}
__device__ __forceinline__ void ldm4(uint32_t* d, uint32_t addr) {
    asm volatile("ldmatrix.sync.aligned.m8n8.x4.shared.b16 {%0,%1,%2,%3}, [%4];"
                 : "=r"(d[0]), "=r"(d[1]), "=r"(d[2]), "=r"(d[3]) : "r"(addr));
}
__device__ __forceinline__ void mma16816(float* c, const uint32_t* a, const uint32_t* b) {
    asm volatile(
        "mma.sync.aligned.m16n8k16.row.col.f32.f16.f16.f32 "
        "{%0,%1,%2,%3}, {%4,%5,%6,%7}, {%8,%9}, {%0,%1,%2,%3};"
        : "+f"(c[0]), "+f"(c[1]), "+f"(c[2]), "+f"(c[3])
        : "r"(a[0]), "r"(a[1]), "r"(a[2]), "r"(a[3]), "r"(b[0]), "r"(b[1]));
}
#define CP16(sa, ga) \
    asm volatile("cp.async.ca.shared.global [%0], [%1], 16;" :: "r"(sa), "l"(ga))
#define CP_COMMIT() asm volatile("cp.async.commit_group;" ::: "memory")
#define CP_WAIT2()  asm volatile("cp.async.wait_group 2;"  ::: "memory")

// ============================================================================
// Templated fp16 HMMA GEMM:  D[128x128 tile] = A(MxK) * B(NxK)^T * cscale
// 3-stage cp.async pipeline (2x16KB per stage = 96KB smem, 2 CTAs/SM).
// MODE 0: plain.  MODE 1: causal score tile skip — dead tiles write their
//         fp32 zero attn tile to Zattn then exit.
// MODE 2: causal K-limit; row tiles REVERSED (heavy tiles scheduled first).
// OUT 0: fp32.  OUT 1: fp16.  OUT 2: fp16 transposed (vhT[b][n][t]) + z offs.
// (R9 mainloop — measured 62.7us / tensor 45% on the 8192x1024x1024.)
// ============================================================================
template<int MODE, int OUT>
__global__ __launch_bounds__(256, 2)
void gemm_t(const __half* __restrict__ Ah, const __half* __restrict__ Bh,
            void* __restrict__ Cout, float* __restrict__ Zattn, float cscale,
            int K, int lda, int ldb, int ldc,
            long long aS1, long long aS2, long long bS1, long long bS2,
            long long cS1, long long cS2)
{
    extern __shared__ char sm[];
    const int tid  = threadIdx.x;
    const int wid  = tid >> 5;
    const int lane = tid & 31;
    const int row0 = (MODE == 2)
        ? ((int)gridDim.y - 1 - (int)blockIdx.y) * 128   // heavy tiles first
        : blockIdx.y * 128;
    const int col0 = blockIdx.x * 128;
    const int z1 = blockIdx.z >> 3, z2 = blockIdx.z & 7;

    if (MODE == 1 && col0 >= row0 + 128) {
        // fully above diagonal: attn is exactly zero here — write it now
        // (rides free under this launch's 3.8%-busy DRAM).
        float* Zb = Zattn + (size_t)z1 * cS1 + (size_t)z2 * cS2
                  + (size_t)row0 * ldc + col0;
        const float4 z4 = make_float4(0.f, 0.f, 0.f, 0.f);
#pragma unroll
        for (int i = 0; i < 16; i++) {
            int id = tid + 256 * i;
            int rr = id >> 5, ccc = (id & 31) * 4;
            *(float4*)(Zb + (size_t)rr * ldc + ccc) = z4;
        }
        return;
    }

    const __half* Ab  = Ah + (size_t)z1 * aS1 + (size_t)z2 * aS2;
    const __half* Bhb = Bh + (size_t)z1 * bS1 + (size_t)z2 * bS2;

    const int Keff = (MODE == 2) ? (row0 + 128 < K ? row0 + 128 : K) : K;
    const int nCh  = Keff >> 6;                      // 64-wide K chunks (>=2)

    const uint32_t sb = smem_u32(sm);

#define FILL(cc) do {                                                         \
        uint32_t stb = sb + (uint32_t)((cc) % 3) * 32768;                     \
        const size_t k0 = (size_t)(cc) << 6;                                  \
        _Pragma("unroll")                                                     \
        for (int i = 0; i < 4; i++) {                                         \
            int id = tid + 256 * i;                                           \
            int rr = id >> 3, sg = id & 7;                                    \
            uint32_t sw = sw128((uint32_t)rr * 128 + sg * 16);                \
            CP16(stb + sw,         Ab  + (size_t)(row0 + rr) * lda + k0 + sg * 8); \
            CP16(stb + 16384 + sw, Bhb + (size_t)(col0 + rr) * ldb + k0 + sg * 8); \
        }                                                                     \
    } while (0)

    // ---- warp tiling: 2 (m) x 4 (n) warps; each 64 rows x 32 cols ----
    const int wm = (wid >> 2) * 64;
    const int wn = (wid & 3) * 32;

    uint32_t aBase[4], bBase[2];
#pragma unroll
    for (int mt = 0; mt < 4; mt++) {
        int r = wm + mt * 16 + ((lane >> 3) & 1) * 8 + (lane & 7);
        aBase[mt] = (uint32_t)r * 128 + (uint32_t)((lane >> 4) * 8) * 2;
    }
#pragma unroll
    for (int np = 0; np < 2; np++) {
        int r = wn + np * 16 + (lane >> 4) * 8 + (lane & 7);
        bBase[np] = (uint32_t)r * 128 + (uint32_t)(((lane >> 3) & 1) * 8) * 2;
    }

    float acc[4][4][4];
#pragma unroll
    for (int mt = 0; mt < 4; mt++)
#pragma unroll
        for (int nt = 0; nt < 4; nt++)
#pragma unroll
            for (int i = 0; i < 4; i++) acc[mt][nt][i] = 0.f;

    // ---- prologue: 3 stages in flight ----
#pragma unroll
    for (int p = 0; p < 3; p++) { if (p < nCh) FILL(p); CP_COMMIT(); }

    for (int c = 0; c < nCh; ++c) {
        CP_WAIT2();
        __syncthreads();
        const uint32_t tb = sb + (uint32_t)(c % 3) * 32768;
#pragma unroll
        for (int ks = 0; ks < 4; ks++) {
            const uint32_t kb2 = (uint32_t)ks * 32;
            uint32_t a[4][4], b2[2][4];
#pragma unroll
            for (int mt = 0; mt < 4; mt++)
                ldm4(a[mt], tb + sw128(aBase[mt] + kb2));
#pragma unroll
            for (int np = 0; np < 2; np++)
                ldm4(b2[np], tb + 16384 + sw128(bBase[np] + kb2));
#pragma unroll
            for (int mt = 0; mt < 4; mt++)
#pragma unroll
                for (int nt = 0; nt < 4; nt++)
                    mma16816(acc[mt][nt], a[mt], &b2[nt >> 1][(nt & 1) * 2]);
        }
        __syncthreads();                // all reads of buf (c%3) done
        int f = c + 3;
        if (f < nCh) FILL(f);
        CP_COMMIT();
    }
#undef FILL

    // ---- epilogue (single variant per instantiation) ----
#pragma unroll
    for (int mt = 0; mt < 4; mt++) {
        const int r = row0 + wm + mt * 16 + (lane >> 2);
#pragma unroll
        for (int nt = 0; nt < 4; nt++) {
            const int cc = col0 + wn + nt * 8 + (lane & 3) * 2;
            float a0 = acc[mt][nt][0], a1 = acc[mt][nt][1];
            float a2 = acc[mt][nt][2], a3 = acc[mt][nt][3];
            if (cscale != 1.f) { a0 *= cscale; a1 *= cscale; a2 *= cscale; a3 *= cscale; }
            if (OUT == 0) {
                float* Cb = (float*)Cout + (size_t)z1 * cS1 + (size_t)z2 * cS2;
                float* p = Cb + (size_t)r * ldc + cc;
                *(float2*)p = make_float2(a0, a1);
                *(float2*)(p + (size_t)8 * ldc) = make_float2(a2, a3);
            } else if (OUT == 1) {
                __half* Cb = (__half*)Cout + (size_t)z1 * cS1 + (size_t)z2 * cS2;
                *(__half2*)(Cb + (size_t)r * ldc + cc) = __floats2half2_rn(a0, a1);
                *(__half2*)(Cb + (size_t)(r + 8) * ldc + cc) = __floats2half2_rn(a2, a3);
            } else {   // vhT[b][n][t]: b = r>>10, t = r&1023  (+ z slab offset)
                __half* CT = (__half*)Cout + (size_t)z1 * cS1 + (size_t)z2 * cS2;
                size_t b0 = (size_t)(r >> 10) * 131072 + (r & 1023);
                CT[b0 + (size_t)cc * 1024]       = __float2half_rn(a0);
                CT[b0 + (size_t)(cc + 1) * 1024] = __float2half_rn(a1);
                size_t b1 = (size_t)((r + 8) >> 10) * 131072 + ((r + 8) & 1023);
                CT[b1 + (size_t)cc * 1024]       = __float2half_rn(a2);
                CT[b1 + (size_t)(cc + 1) * 1024] = __float2half_rn(a3);
            }
        }
    }
}

// ============================================================================
// fp32 -> fp16 convert; blockIdx.y selects one of 3 (in,out) pairs
// ============================================================================
__global__ __launch_bounds__(256)
void conv_h3(const float* __restrict__ i0, __half* __restrict__ o0,
             const float* __restrict__ i1, __half* __restrict__ o1,
             const float* __restrict__ i2, __half* __restrict__ o2)
{
    const float* in  = blockIdx.y == 0 ? i0 : (blockIdx.y == 1 ? i1 : i2);
    __half*      out = blockIdx.y == 0 ? o0 : (blockIdx.y == 1 ? o1 : o2);
    const size_t i = ((size_t)blockIdx.x * 256 + threadIdx.x) * 4;
    float4 v = *(const float4*)(in + i);
    *(__half2*)(out + i)     = __floats2half2_rn(v.x, v.y);
    *(__half2*)(out + i + 2) = __floats2half2_rn(v.z, v.w);
}

// ============================================================================
// Merged weight transpose: z<8 Wq[z], z<16 Wk[z-8], z==16 Wv (all 1024x128),
// z==17 Wo (128x1024, block indices swapped).
// ============================================================================
__global__ __launch_bounds__(256)
void transpose_w18(const float* __restrict__ Wq, const float* __restrict__ Wk,
                   const float* __restrict__ Wv, const float* __restrict__ Wo,
                   __half* __restrict__ wqh, __half* __restrict__ wkh,
                   __half* __restrict__ wvh, __half* __restrict__ woh)
{
    __shared__ float t[32][33];
    const int z = blockIdx.z;
    const float* in; __half* out;
    int R, C, r0, c0;
    if (z < 8)       { in = Wq + (size_t)z * 131072;       out = wqh + (size_t)z * 131072;
                       R = 1024; C = 128; r0 = blockIdx.y * 32; c0 = blockIdx.x * 32; }
    else if (z < 16) { in = Wk + (size_t)(z - 8) * 131072; out = wkh + (size_t)(z - 8) * 131072;
                       R = 1024; C = 128; r0 = blockIdx.y * 32; c0 = blockIdx.x * 32; }
    else if (z == 16){ in = Wv;                            out = wvh;
                       R = 1024; C = 128; r0 = blockIdx.y * 32; c0 = blockIdx.x * 32; }
    else             { in = Wo;                            out = woh;
                       R = 128;  C = 1024; r0 = blockIdx.x * 32; c0 = blockIdx.y * 32; }
    const int tx = threadIdx.x, ty = threadIdx.y;
#pragma unroll
    for (int i = 0; i < 32; i += 8)
        t[ty + i][tx] = in[(size_t)(r0 + ty + i) * C + c0 + tx];
    __syncthreads();
#pragma unroll
    for (int i = 0; i < 32; i += 8)
        out[(size_t)(c0 + ty + i) * R + r0 + tx] = __float2half_rn(t[tx][ty + i]);
}

// ============================================================================
// Combine 4 split-K vhT partials (fp16) -> vth fp16.
// ============================================================================
__global__ __launch_bounds__(256)
void combine_vtp(const __half2* __restrict__ vtp, __half2* __restrict__ vth)
{
    const size_t i = (size_t)blockIdx.x * 256 + threadIdx.x;   // half2 units
    float sx = 0.f, sy = 0.f;
#pragma unroll
    for (int s = 0; s < 4; s++) {
        __half2 v = vtp[(size_t)s * (MROWS * DK / 2) + i];
        sx += __low2float(v);
        sy += __high2float(v);
    }
    vth[i] = __floats2half2_rn(sx, sy);
}

// ============================================================================
// Causal softmax (UNCONDITIONAL batched row reads, MLP=16 — do not guard the
// loads; guarded loads cost ~33us, see R10/R12). Writes fp32 attn and fp16 P
// in-place into sc ONLY up to the causal 128-block edge (predicated stores —
// measured free). Zeros above the edge are written by the scores GEMM's dead
// tiles. One warp per row.
// ============================================================================
__global__ __launch_bounds__(256)
void softmax_kernel(__half* __restrict__ sc, float* __restrict__ attn)
{
    const int gw   = blockIdx.x * 8 + (threadIdx.x >> 5);
    const int lane = threadIdx.x & 31;
    const int t    = gw & (TT - 1);
    __half2* srow = (__half2*)(sc + (size_t)gw * TT);
    float*   arow = attn + (size_t)gw * TT;

    float2 v[16];
    float m = -1e30f;
#pragma unroll
    for (int i = 0; i < 16; i++) {
        const int pi = i * 32 + lane;          // half2 index; s = 2*pi, 2*pi+1
        __half2 h = srow[pi];
        v[i].x = (2 * pi     <= t) ? __low2float(h)  : -1e30f;
        v[i].y = (2 * pi + 1 <= t) ? __high2float(h) : -1e30f;
        m = fmaxf(m, fmaxf(v[i].x, v[i].y));
    }
#pragma unroll
    for (int o = 16; o; o >>= 1) m = fmaxf(m, __shfl_xor_sync(~0u, m, o));

    const float scale = 0.08838834764831845f;   // 1/sqrt(128)
    float sum = 0.f;
#pragma unroll
    for (int i = 0; i < 16; i++) {
        const int pi = i * 32 + lane;
        float e0 = (2 * pi     <= t) ? __expf((v[i].x - m) * scale) : 0.f;
        float e1 = (2 * pi + 1 <= t) ? __expf((v[i].y - m) * scale) : 0.f;
        v[i].x = e0; v[i].y = e1;
        sum += e0 + e1;
    }
#pragma unroll
    for (int o = 16; o; o >>= 1) sum += __shfl_xor_sync(~0u, sum, o);
    const float rinv = 1.0f / sum;

    const int plim = (((t >> 7) + 1) << 6);     // half2 units inside causal blocks
#pragma unroll
    for (int i = 0; i < 16; i++) {
        const int pi = i * 32 + lane;
        if (pi < plim) {
            float p0 = v[i].x * rinv, p1 = v[i].y * rinv;
            *(float2*)(arow + 2 * pi) = make_float2(p0, p1);
            srow[pi] = __floats2half2_rn(p0, p1);
        }
    }
}

// ============================================================================
// Head mean over fp16 oh -> fp16 om. 2 elems (half2) per thread.
// ============================================================================
__global__ __launch_bounds__(256)
void reduce_mean_h(const __half2* __restrict__ oh, __half2* __restrict__ om)
{
    const size_t i = (size_t)blockIdx.x * 256 + threadIdx.x;   // half2 units
    float sx = 0.f, sy = 0.f;
#pragma unroll
    for (int h = 0; h < NH; h++) {
        __half2 v = oh[(size_t)h * (MROWS * DK / 2) + i];
        sx += __low2float(v);
        sy += __high2float(v);
    }
    om[i] = __floats2half2_rn(sx * 0.125f, sy * 0.125f);
}

// ============================================================================
extern "C" void kernel_launch(void* const* d_in, const int* in_sizes, int n_in,
                              void* d_out, int out_size)
{
    const float* q  = (const float*)d_in[0];
    const float* k  = (const float*)d_in[1];
    const float* v  = (const float*)d_in[2];
    /* d_in[3] = mask: exact causal tril; handled analytically */
    const float* Wq = (const float*)d_in[4];
    const float* Wk = (const float*)d_in[5];
    const float* Wv = (const float*)d_in[6];
    const float* Wo = (const float*)d_in[7];

    float* out  = (float*)d_out;                       // (B,T,DM)
    float* attn = out + (size_t)MROWS * DM;            // (H,B,T,S)

    __half *q2,*k2,*v2,*wqh,*wkh,*wvh,*woh,*qh,*khh,*vtp,*vth,*sc,*oh,*om;
    cudaGetSymbolAddress((void**)&q2,  g_q2);
    cudaGetSymbolAddress((void**)&k2,  g_k2);
    cudaGetSymbolAddress((void**)&v2,  g_v2);
    cudaGetSymbolAddress((void**)&wqh, g_wqh);
    cudaGetSymbolAddress((void**)&wkh, g_wkh);
    cudaGetSymbolAddress((void**)&wvh, g_wvh);
    cudaGetSymbolAddress((void**)&woh, g_woh);
    cudaGetSymbolAddress((void**)&qh,  g_qh);
    cudaGetSymbolAddress((void**)&khh, g_khh);
    cudaGetSymbolAddress((void**)&vtp, g_vtp);
    cudaGetSymbolAddress((void**)&vth, g_vth);
    cudaGetSymbolAddress((void**)&sc,  g_sc);
    cudaGetSymbolAddress((void**)&oh,  g_oh);
    cudaGetSymbolAddress((void**)&om,  g_om);

    const int GSM = 3 * 2 * 16384;                     // 96 KB dynamic smem
    cudaFuncSetAttribute(gemm_t<0,0>, cudaFuncAttributeMaxDynamicSharedMemorySize, GSM);
    cudaFuncSetAttribute(gemm_t<0,1>, cudaFuncAttributeMaxDynamicSharedMemorySize, GSM);
    cudaFuncSetAttribute(gemm_t<0,2>, cudaFuncAttributeMaxDynamicSharedMemorySize, GSM);
    cudaFuncSetAttribute(gemm_t<1,1>, cudaFuncAttributeMaxDynamicSharedMemorySize, GSM);
    cudaFuncSetAttribute(gemm_t<2,1>, cudaFuncAttributeMaxDynamicSharedMemorySize, GSM);

    dim3 tb(32, 8);

    // ---- operand preparation ----
    conv_h3<<<dim3(MROWS * DM / 1024, 3), 256>>>(q, q2, k, k2, v, v2);
    transpose_w18<<<dim3(4, 32, 18), tb>>>(Wq, Wk, Wv, Wo, wqh, wkh, wvh, woh);

    // ---- projections ----
    gemm_t<0,1><<<dim3(8, 64, 1), 256, GSM>>>(q2, wqh, qh, nullptr, 1.f,
                                              1024, 1024, 1024, 1024,
                                              0,0, 0,0, 0,0);
    gemm_t<0,1><<<dim3(8, 64, 1), 256, GSM>>>(k2, wkh, khh, nullptr, 1.f,
                                              1024, 1024, 1024, 1024,
                                              0,0, 0,0, 0,0);
    // V projection: split-K x4 (z2 = K slab), partials -> vtp, then combine.
    gemm_t<0,2><<<dim3(1, 64, 4), 256, GSM>>>(v2, wvh, vtp, nullptr, 1.f,
                                              256, 1024, 1024, 128,
                                              0, 256LL,             // A: +k slab
                                              0, 256LL,             // B: +k slab
                                              0, 1048576LL);        // C: partial
    combine_vtp<<<dim3((MROWS * DK / 2) / 256), 256>>>(
        (const __half2*)vtp, (__half2*)vth);

    // ---- scores = qh @ kh^T -> fp16 sc; dead tiles zero-fill attn ----
    gemm_t<1,1><<<dim3(8, 8, 64), 256, GSM>>>(qh, khh, sc, attn, 1.f,
                                              128, 1024, 1024, 1024,
                                              1048576LL, 128LL,      // A: b, h
                                              1048576LL, 128LL,      // B: b, h
                                              1048576LL, 8388608LL); // C: b, h

    // ---- softmax: sc(fp16) -> attn(fp32, causal range) + P into sc ----
    softmax_kernel<<<dim3(NH * BB * TT / 8), 256>>>(sc, attn);

    // ---- O_h = P @ V  (per-head, causal K limit, heavy rows first) ----
    gemm_t<2,1><<<dim3(1, 8, 64), 256, GSM>>>(sc, vth, oh, nullptr, 1.f,
                                              1024, 1024, 1024, 128,
                                              1048576LL, 8388608LL,  // A: b, h
                                              131072LL,  0LL,        // B: b
                                              131072LL,  1048576LL); // C: b, h

    // ---- head mean (fp16 in/out) ----
    reduce_mean_h<<<dim3((MROWS * DK / 2) / 256), 256>>>(
        (const __half2*)oh, (__half2*)om);

    // ---- out = Om @ Wo ----
    gemm_t<0,0><<<dim3(8, 64, 1), 256, GSM>>>(om, woh, out, nullptr, 1.f,
                                              128, 128, 128, 1024,
                                              0,0, 0,0, 0,0);
}

// round 16
// speedup vs baseline: 1.1976x; 1.0726x over previous
#include <cuda_runtime.h>
#include <cuda_fp16.h>
#include <stdint.h>
#include <math.h>

#define BB 8
#define TT 1024
#define DM 1024
#define NH 8
#define DK 128
#define MROWS (BB*TT)   /* 8192 */

// ---------------- scratch (device globals; no cudaMalloc allowed) ----------
__device__ __half g_q2 [(size_t)MROWS * DM];        // 16 MB
__device__ __half g_k2 [(size_t)MROWS * DM];        // 16 MB
__device__ __half g_v2 [(size_t)MROWS * DM];        // 16 MB
__device__ __half g_wqh[(size_t)NH * DM * DK];      // 2 MB  [h][128][1024]
__device__ __half g_wkh[(size_t)NH * DM * DK];      // 2 MB
__device__ __half g_wvh[(size_t)DM * DK];           // [128][1024]
__device__ __half g_woh[(size_t)DM * DK];           // [1024][128]
__device__ __half g_qh [(size_t)MROWS * DM];        // 16 MB  qh (A of scores)
__device__ __half g_khh[(size_t)MROWS * DM];        // 16 MB  kh (B of scores)
__device__ __half g_vtp[(size_t)4 * MROWS * DK];    // 8 MB   vhT split-K partials
__device__ __half g_vth[(size_t)MROWS * DK];        // 2 MB   vhT [b][128][1024]
__device__ __half g_sc [(size_t)NH * BB * TT * TT]; // 134 MB scores fp16 -> P in place
__device__ __half g_oh [(size_t)NH * MROWS * DK];   // 16 MB  per-head O (fp16)
__device__ __half g_om [(size_t)MROWS * DK];        // 2 MB   head-mean fp16

// ======================= helpers ==============================
__device__ __forceinline__ uint32_t smem_u32(const void* p) {
    uint32_t a;
    asm("{ .reg .u64 t; cvta.to.shared.u64 t, %1; cvt.u32.u64 %0, t; }"
        : "=r"(a) : "l"(p));
    return a;
}
__device__ __forceinline__ uint32_t sw128(uint32_t off) {
    return off ^ ((off >> 3) & 0x70);
}
__device__ __forceinline__ void ldm4(uint32_t* d, uint32_t addr) {
    asm volatile("ldmatrix.sync.aligned.m8n8.x4.shared.b16 {%0,%1,%2,%3}, [%4];"
                 : "=r"(d[0]), "=r"(d[1]), "=r"(d[2]), "=r"(d[3]) : "r"(addr));
}
__device__ __forceinline__ void mma16816(float* c, const uint32_t* a, const uint32_t* b) {
    asm volatile(
        "mma.sync.aligned.m16n8k16.row.col.f32.f16.f16.f32 "
        "{%0,%1,%2,%3}, {%4,%5,%6,%7}, {%8,%9}, {%0,%1,%2,%3};"
        : "+f"(c[0]), "+f"(c[1]), "+f"(c[2]), "+f"(c[3])
        : "r"(a[0]), "r"(a[1]), "r"(a[2]), "r"(a[3]), "r"(b[0]), "r"(b[1]));
}
#define CP16(sa, ga) \
    asm volatile("cp.async.ca.shared.global [%0], [%1], 16;" :: "r"(sa), "l"(ga))
#define CP_COMMIT() asm volatile("cp.async.commit_group;" ::: "memory")
#define CP_WAIT2()  asm volatile("cp.async.wait_group 2;"  ::: "memory")

// ============================================================================
// Templated fp16 HMMA GEMM:  D[128x128 tile] = A(MxK) * B(NxK)^T * cscale
// 3-stage cp.async pipeline (2x16KB per stage = 96KB smem, 2 CTAs/SM).
// MODE 0: plain.  MODE 1: causal score tile skip — dead tiles write their
//         fp32 zero attn tile to Zattn then exit.
// MODE 2: causal K-limit; row tiles REVERSED (heavy tiles scheduled first).
// OUT 0: fp32.  OUT 1: fp16.  OUT 2: fp16 transposed (vhT[b][n][t]) + z offs.
// (R9 mainloop — measured 62.7us / tensor 45% on the 8192x1024x1024.)
// ============================================================================
template<int MODE, int OUT>
__global__ __launch_bounds__(256, 2)
void gemm_t(const __half* __restrict__ Ah, const __half* __restrict__ Bh,
            void* __restrict__ Cout, float* __restrict__ Zattn, float cscale,
            int K, int lda, int ldb, int ldc,
            long long aS1, long long aS2, long long bS1, long long bS2,
            long long cS1, long long cS2)
{
    extern __shared__ char sm[];
    const int tid  = threadIdx.x;
    const int wid  = tid >> 5;
    const int lane = tid & 31;
    const int row0 = (MODE == 2)
        ? ((int)gridDim.y - 1 - (int)blockIdx.y) * 128   // heavy tiles first
        : blockIdx.y * 128;
    const int col0 = blockIdx.x * 128;
    const int z1 = blockIdx.z >> 3, z2 = blockIdx.z & 7;

    if (MODE == 1 && col0 >= row0 + 128) {
        // fully above diagonal: attn is exactly zero here — write it now
        // (rides free under this launch's 3.8%-busy DRAM).
        float* Zb = Zattn + (size_t)z1 * cS1 + (size_t)z2 * cS2
                  + (size_t)row0 * ldc + col0;
        const float4 z4 = make_float4(0.f, 0.f, 0.f, 0.f);
#pragma unroll
        for (int i = 0; i < 16; i++) {
            int id = tid + 256 * i;
            int rr = id >> 5, ccc = (id & 31) * 4;
            *(float4*)(Zb + (size_t)rr * ldc + ccc) = z4;
        }
        return;
    }

    const __half* Ab  = Ah + (size_t)z1 * aS1 + (size_t)z2 * aS2;
    const __half* Bhb = Bh + (size_t)z1 * bS1 + (size_t)z2 * bS2;

    const int Keff = (MODE == 2) ? (row0 + 128 < K ? row0 + 128 : K) : K;
    const int nCh  = Keff >> 6;                      // 64-wide K chunks (>=2)

    const uint32_t sb = smem_u32(sm);

#define FILL(cc) do {                                                         \
        uint32_t stb = sb + (uint32_t)((cc) % 3) * 32768;                     \
        const size_t k0 = (size_t)(cc) << 6;                                  \
        _Pragma("unroll")                                                     \
        for (int i = 0; i < 4; i++) {                                         \
            int id = tid + 256 * i;                                           \
            int rr = id >> 3, sg = id & 7;                                    \
            uint32_t sw = sw128((uint32_t)rr * 128 + sg * 16);                \
            CP16(stb + sw,         Ab  + (size_t)(row0 + rr) * lda + k0 + sg * 8); \
            CP16(stb + 16384 + sw, Bhb + (size_t)(col0 + rr) * ldb + k0 + sg * 8); \
        }                                                                     \
    } while (0)

    // ---- warp tiling: 2 (m) x 4 (n) warps; each 64 rows x 32 cols ----
    const int wm = (wid >> 2) * 64;
    const int wn = (wid & 3) * 32;

    uint32_t aBase[4], bBase[2];
#pragma unroll
    for (int mt = 0; mt < 4; mt++) {
        int r = wm + mt * 16 + ((lane >> 3) & 1) * 8 + (lane & 7);
        aBase[mt] = (uint32_t)r * 128 + (uint32_t)((lane >> 4) * 8) * 2;
    }
#pragma unroll
    for (int np = 0; np < 2; np++) {
        int r = wn + np * 16 + (lane >> 4) * 8 + (lane & 7);
        bBase[np] = (uint32_t)r * 128 + (uint32_t)(((lane >> 3) & 1) * 8) * 2;
    }

    float acc[4][4][4];
#pragma unroll
    for (int mt = 0; mt < 4; mt++)
#pragma unroll
        for (int nt = 0; nt < 4; nt++)
#pragma unroll
            for (int i = 0; i < 4; i++) acc[mt][nt][i] = 0.f;

    // ---- prologue: 3 stages in flight ----
#pragma unroll
    for (int p = 0; p < 3; p++) { if (p < nCh) FILL(p); CP_COMMIT(); }

    for (int c = 0; c < nCh; ++c) {
        CP_WAIT2();
        __syncthreads();
        const uint32_t tb = sb + (uint32_t)(c % 3) * 32768;
#pragma unroll
        for (int ks = 0; ks < 4; ks++) {
            const uint32_t kb2 = (uint32_t)ks * 32;
            uint32_t a[4][4], b2[2][4];
#pragma unroll
            for (int mt = 0; mt < 4; mt++)
                ldm4(a[mt], tb + sw128(aBase[mt] + kb2));
#pragma unroll
            for (int np = 0; np < 2; np++)
                ldm4(b2[np], tb + 16384 + sw128(bBase[np] + kb2));
#pragma unroll
            for (int mt = 0; mt < 4; mt++)
#pragma unroll
                for (int nt = 0; nt < 4; nt++)
                    mma16816(acc[mt][nt], a[mt], &b2[nt >> 1][(nt & 1) * 2]);
        }
        __syncthreads();                // all reads of buf (c%3) done
        int f = c + 3;
        if (f < nCh) FILL(f);
        CP_COMMIT();
    }
#undef FILL

    // ---- epilogue (single variant per instantiation) ----
#pragma unroll
    for (int mt = 0; mt < 4; mt++) {
        const int r = row0 + wm + mt * 16 + (lane >> 2);
#pragma unroll
        for (int nt = 0; nt < 4; nt++) {
            const int cc = col0 + wn + nt * 8 + (lane & 3) * 2;
            float a0 = acc[mt][nt][0], a1 = acc[mt][nt][1];
            float a2 = acc[mt][nt][2], a3 = acc[mt][nt][3];
            if (cscale != 1.f) { a0 *= cscale; a1 *= cscale; a2 *= cscale; a3 *= cscale; }
            if (OUT == 0) {
                float* Cb = (float*)Cout + (size_t)z1 * cS1 + (size_t)z2 * cS2;
                float* p = Cb + (size_t)r * ldc + cc;
                *(float2*)p = make_float2(a0, a1);
                *(float2*)(p + (size_t)8 * ldc) = make_float2(a2, a3);
            } else if (OUT == 1) {
                __half* Cb = (__half*)Cout + (size_t)z1 * cS1 + (size_t)z2 * cS2;
                *(__half2*)(Cb + (size_t)r * ldc + cc) = __floats2half2_rn(a0, a1);
                *(__half2*)(Cb + (size_t)(r + 8) * ldc + cc) = __floats2half2_rn(a2, a3);
            } else {   // vhT[b][n][t]: b = r>>10, t = r&1023  (+ z slab offset)
                __half* CT = (__half*)Cout + (size_t)z1 * cS1 + (size_t)z2 * cS2;
                size_t b0 = (size_t)(r >> 10) * 131072 + (r & 1023);
                CT[b0 + (size_t)cc * 1024]       = __float2half_rn(a0);
                CT[b0 + (size_t)(cc + 1) * 1024] = __float2half_rn(a1);
                size_t b1 = (size_t)((r + 8) >> 10) * 131072 + ((r + 8) & 1023);
                CT[b1 + (size_t)cc * 1024]       = __float2half_rn(a2);
                CT[b1 + (size_t)(cc + 1) * 1024] = __float2half_rn(a3);
            }
        }
    }
}

// ============================================================================
// fp32 -> fp16 convert; blockIdx.y selects one of 3 (in,out) pairs
// ============================================================================
__global__ __launch_bounds__(256)
void conv_h3(const float* __restrict__ i0, __half* __restrict__ o0,
             const float* __restrict__ i1, __half* __restrict__ o1,
             const float* __restrict__ i2, __half* __restrict__ o2)
{
    const float* in  = blockIdx.y == 0 ? i0 : (blockIdx.y == 1 ? i1 : i2);
    __half*      out = blockIdx.y == 0 ? o0 : (blockIdx.y == 1 ? o1 : o2);
    const size_t i = ((size_t)blockIdx.x * 256 + threadIdx.x) * 4;
    float4 v = *(const float4*)(in + i);
    *(__half2*)(out + i)     = __floats2half2_rn(v.x, v.y);
    *(__half2*)(out + i + 2) = __floats2half2_rn(v.z, v.w);
}

// ============================================================================
// Merged weight transpose: z<8 Wq[z], z<16 Wk[z-8], z==16 Wv (all 1024x128),
// z==17 Wo (128x1024, block indices swapped).
// ============================================================================
__global__ __launch_bounds__(256)
void transpose_w18(const float* __restrict__ Wq, const float* __restrict__ Wk,
                   const float* __restrict__ Wv, const float* __restrict__ Wo,
                   __half* __restrict__ wqh, __half* __restrict__ wkh,
                   __half* __restrict__ wvh, __half* __restrict__ woh)
{
    __shared__ float t[32][33];
    const int z = blockIdx.z;
    const float* in; __half* out;
    int R, C, r0, c0;
    if (z < 8)       { in = Wq + (size_t)z * 131072;       out = wqh + (size_t)z * 131072;
                       R = 1024; C = 128; r0 = blockIdx.y * 32; c0 = blockIdx.x * 32; }
    else if (z < 16) { in = Wk + (size_t)(z - 8) * 131072; out = wkh + (size_t)(z - 8) * 131072;
                       R = 1024; C = 128; r0 = blockIdx.y * 32; c0 = blockIdx.x * 32; }
    else if (z == 16){ in = Wv;                            out = wvh;
                       R = 1024; C = 128; r0 = blockIdx.y * 32; c0 = blockIdx.x * 32; }
    else             { in = Wo;                            out = woh;
                       R = 128;  C = 1024; r0 = blockIdx.x * 32; c0 = blockIdx.y * 32; }
    const int tx = threadIdx.x, ty = threadIdx.y;
#pragma unroll
    for (int i = 0; i < 32; i += 8)
        t[ty + i][tx] = in[(size_t)(r0 + ty + i) * C + c0 + tx];
    __syncthreads();
#pragma unroll
    for (int i = 0; i < 32; i += 8)
        out[(size_t)(c0 + ty + i) * R + r0 + tx] = __float2half_rn(t[tx][ty + i]);
}

// ============================================================================
// Combine 4 split-K vhT partials (fp16) -> vth fp16.
// ============================================================================
__global__ __launch_bounds__(256)
void combine_vtp(const __half2* __restrict__ vtp, __half2* __restrict__ vth)
{
    const size_t i = (size_t)blockIdx.x * 256 + threadIdx.x;   // half2 units
    float sx = 0.f, sy = 0.f;
#pragma unroll
    for (int s = 0; s < 4; s++) {
        __half2 v = vtp[(size_t)s * (MROWS * DK / 2) + i];
        sx += __low2float(v);
        sy += __high2float(v);
    }
    vth[i] = __floats2half2_rn(sx, sy);
}

// ============================================================================
// Causal softmax — two fully-unrolled straight-line bodies selected by a
// warp-uniform branch (rows t<512 touch only the first 8 chunks). Loads are
// UNCONDITIONAL and front-batched inside each body (guarded loads cost ~33us,
// see R10/R12). Stores predicated to the causal 128-block edge (free). Zeros
// above the edge come from the scores GEMM's dead tiles. One warp per row.
// ============================================================================
template<int NCH>
__device__ __forceinline__ void softmax_body(__half2* __restrict__ srow,
                                             float* __restrict__ arow,
                                             int t, int lane)
{
    float2 v[NCH];
    float m = -1e30f;
#pragma unroll
    for (int i = 0; i < NCH; i++) {
        const int pi = i * 32 + lane;          // half2 index; s = 2*pi, 2*pi+1
        __half2 h = srow[pi];
        v[i].x = (2 * pi     <= t) ? __low2float(h)  : -1e30f;
        v[i].y = (2 * pi + 1 <= t) ? __high2float(h) : -1e30f;
        m = fmaxf(m, fmaxf(v[i].x, v[i].y));
    }
#pragma unroll
    for (int o = 16; o; o >>= 1) m = fmaxf(m, __shfl_xor_sync(~0u, m, o));

    const float scale = 0.08838834764831845f;   // 1/sqrt(128)
    float sum = 0.f;
#pragma unroll
    for (int i = 0; i < NCH; i++) {
        const int pi = i * 32 + lane;
        float e0 = (2 * pi     <= t) ? __expf((v[i].x - m) * scale) : 0.f;
        float e1 = (2 * pi + 1 <= t) ? __expf((v[i].y - m) * scale) : 0.f;
        v[i].x = e0; v[i].y = e1;
        sum += e0 + e1;
    }
#pragma unroll
    for (int o = 16; o; o >>= 1) sum += __shfl_xor_sync(~0u, sum, o);
    const float rinv = 1.0f / sum;

    const int plim = (((t >> 7) + 1) << 6);     // half2 units inside causal blocks
#pragma unroll
    for (int i = 0; i < NCH; i++) {
        const int pi = i * 32 + lane;
        if (pi < plim) {
            float p0 = v[i].x * rinv, p1 = v[i].y * rinv;
            *(float2*)(arow + 2 * pi) = make_float2(p0, p1);
            srow[pi] = __floats2half2_rn(p0, p1);
        }
    }
}

__global__ __launch_bounds__(256)
void softmax_kernel(__half* __restrict__ sc, float* __restrict__ attn)
{
    const int gw   = blockIdx.x * 8 + (threadIdx.x >> 5);
    const int lane = threadIdx.x & 31;
    const int t    = gw & (TT - 1);
    __half2* srow = (__half2*)(sc + (size_t)gw * TT);
    float*   arow = attn + (size_t)gw * TT;

    if (t < 512) softmax_body<8>(srow, arow, t, lane);
    else         softmax_body<16>(srow, arow, t, lane);
}

// ============================================================================
// Head mean over fp16 oh -> fp16 om. 2 elems (half2) per thread.
// ============================================================================
__global__ __launch_bounds__(256)
void reduce_mean_h(const __half2* __restrict__ oh, __half2* __restrict__ om)
{
    const size_t i = (size_t)blockIdx.x * 256 + threadIdx.x;   // half2 units
    float sx = 0.f, sy = 0.f;
#pragma unroll
    for (int h = 0; h < NH; h++) {
        __half2 v = oh[(size_t)h * (MROWS * DK / 2) + i];
        sx += __low2float(v);
        sy += __high2float(v);
    }
    om[i] = __floats2half2_rn(sx * 0.125f, sy * 0.125f);
}

// ============================================================================
extern "C" void kernel_launch(void* const* d_in, const int* in_sizes, int n_in,
                              void* d_out, int out_size)
{
    const float* q  = (const float*)d_in[0];
    const float* k  = (const float*)d_in[1];
    const float* v  = (const float*)d_in[2];
    /* d_in[3] = mask: exact causal tril; handled analytically */
    const float* Wq = (const float*)d_in[4];
    const float* Wk = (const float*)d_in[5];
    const float* Wv = (const float*)d_in[6];
    const float* Wo = (const float*)d_in[7];

    float* out  = (float*)d_out;                       // (B,T,DM)
    float* attn = out + (size_t)MROWS * DM;            // (H,B,T,S)

    __half *q2,*k2,*v2,*wqh,*wkh,*wvh,*woh,*qh,*khh,*vtp,*vth,*sc,*oh,*om;
    cudaGetSymbolAddress((void**)&q2,  g_q2);
    cudaGetSymbolAddress((void**)&k2,  g_k2);
    cudaGetSymbolAddress((void**)&v2,  g_v2);
    cudaGetSymbolAddress((void**)&wqh, g_wqh);
    cudaGetSymbolAddress((void**)&wkh, g_wkh);
    cudaGetSymbolAddress((void**)&wvh, g_wvh);
    cudaGetSymbolAddress((void**)&woh, g_woh);
    cudaGetSymbolAddress((void**)&qh,  g_qh);
    cudaGetSymbolAddress((void**)&khh, g_khh);
    cudaGetSymbolAddress((void**)&vtp, g_vtp);
    cudaGetSymbolAddress((void**)&vth, g_vth);
    cudaGetSymbolAddress((void**)&sc,  g_sc);
    cudaGetSymbolAddress((void**)&oh,  g_oh);
    cudaGetSymbolAddress((void**)&om,  g_om);

    const int GSM = 3 * 2 * 16384;                     // 96 KB dynamic smem
    cudaFuncSetAttribute(gemm_t<0,0>, cudaFuncAttributeMaxDynamicSharedMemorySize, GSM);
    cudaFuncSetAttribute(gemm_t<0,1>, cudaFuncAttributeMaxDynamicSharedMemorySize, GSM);
    cudaFuncSetAttribute(gemm_t<0,2>, cudaFuncAttributeMaxDynamicSharedMemorySize, GSM);
    cudaFuncSetAttribute(gemm_t<1,1>, cudaFuncAttributeMaxDynamicSharedMemorySize, GSM);
    cudaFuncSetAttribute(gemm_t<2,1>, cudaFuncAttributeMaxDynamicSharedMemorySize, GSM);

    dim3 tb(32, 8);

    // ---- operand preparation ----
    conv_h3<<<dim3(MROWS * DM / 1024, 3), 256>>>(q, q2, k, k2, v, v2);
    transpose_w18<<<dim3(4, 32, 18), tb>>>(Wq, Wk, Wv, Wo, wqh, wkh, wvh, woh);

    // ---- Q + K projections, ONE launch (z2 = 0:Q, 1:K via pointer diffs) ----
    const long long dA = (long long)(k2  - q2);        // element diffs
    const long long dB = (long long)(wkh - wqh);
    const long long dC = (long long)(khh - qh);
    gemm_t<0,1><<<dim3(8, 64, 2), 256, GSM>>>(q2, wqh, qh, nullptr, 1.f,
                                              1024, 1024, 1024, 1024,
                                              0, dA, 0, dB, 0, dC);

    // V projection: split-K x4 (z2 = K slab), partials -> vtp, then combine.
    gemm_t<0,2><<<dim3(1, 64, 4), 256, GSM>>>(v2, wvh, vtp, nullptr, 1.f,
                                              256, 1024, 1024, 128,
                                              0, 256LL,             // A: +k slab
                                              0, 256LL,             // B: +k slab
                                              0, 1048576LL);        // C: partial
    combine_vtp<<<dim3((MROWS * DK / 2) / 256), 256>>>(
        (const __half2*)vtp, (__half2*)vth);

    // ---- scores = qh @ kh^T -> fp16 sc; dead tiles zero-fill attn ----
    gemm_t<1,1><<<dim3(8, 8, 64), 256, GSM>>>(qh, khh, sc, attn, 1.f,
                                              128, 1024, 1024, 1024,
                                              1048576LL, 128LL,      // A: b, h
                                              1048576LL, 128LL,      // B: b, h
                                              1048576LL, 8388608LL); // C: b, h

    // ---- softmax: sc(fp16) -> attn(fp32, causal range) + P into sc ----
    softmax_kernel<<<dim3(NH * BB * TT / 8), 256>>>(sc, attn);

    // ---- O_h = P @ V  (per-head, causal K limit, heavy rows first) ----
    gemm_t<2,1><<<dim3(1, 8, 64), 256, GSM>>>(sc, vth, oh, nullptr, 1.f,
                                              1024, 1024, 1024, 128,
                                              1048576LL, 8388608LL,  // A: b, h
                                              131072LL,  0LL,        // B: b
                                              131072LL,  1048576LL); // C: b, h

    // ---- head mean (fp16 in/out) ----
    reduce_mean_h<<<dim3((MROWS * DK / 2) / 256), 256>>>(
        (const __half2*)oh, (__half2*)om);

    // ---- out = Om @ Wo ----
    gemm_t<0,0><<<dim3(8, 64, 1), 256, GSM>>>(om, woh, out, nullptr, 1.f,
                                              128, 128, 128, 1024,
                                              0,0, 0,0, 0,0);
}

// round 17
// speedup vs baseline: 1.2008x; 1.0027x over previous
#include <cuda_runtime.h>
#include <cuda_fp16.h>
#include <stdint.h>
#include <math.h>

#define BB 8
#define TT 1024
#define DM 1024
#define NH 8
#define DK 128
#define MROWS (BB*TT)   /* 8192 */

// ---------------- scratch (device globals; no cudaMalloc allowed) ----------
__device__ __half g_q2 [(size_t)MROWS * DM];        // 16 MB
__device__ __half g_k2 [(size_t)MROWS * DM];        // 16 MB
__device__ __half g_v2 [(size_t)MROWS * DM];        // 16 MB
__device__ __half g_wqh[(size_t)NH * DM * DK];      // 2 MB  [h][128][1024]
__device__ __half g_wkh[(size_t)NH * DM * DK];      // 2 MB
__device__ __half g_wvh[(size_t)DM * DK];           // [128][1024]
__device__ __half g_woh[(size_t)DM * DK];           // [1024][128]
__device__ __half g_qh [(size_t)MROWS * DM];        // 16 MB  qh (A of scores)
__device__ __half g_khh[(size_t)MROWS * DM];        // 16 MB  kh (B of scores)
__device__ __half g_vtp[(size_t)4 * MROWS * DK];    // 8 MB   vh split-K partials (row-major)
__device__ __half g_vth[(size_t)MROWS * DK];        // 2 MB   vhT [b][128][1024]
__device__ __half g_sc [(size_t)NH * BB * TT * TT]; // 134 MB scores fp16 -> P in place
__device__ __half g_oh [(size_t)NH * MROWS * DK];   // 16 MB  per-head O (fp16)
__device__ __half g_om [(size_t)MROWS * DK];        // 2 MB   head-mean fp16

// ======================= helpers ==============================
__device__ __forceinline__ uint32_t smem_u32(const void* p) {
    uint32_t a;
    asm("{ .reg .u64 t; cvta.to.shared.u64 t, %1; cvt.u32.u64 %0, t; }"
        : "=r"(a) : "l"(p));
    return a;
}
__device__ __forceinline__ uint32_t sw128(uint32_t off) {
    return off ^ ((off >> 3) & 0x70);
}
__device__ __forceinline__ void ldm4(uint32_t* d, uint32_t addr) {
    asm volatile("ldmatrix.sync.aligned.m8n8.x4.shared.b16 {%0,%1,%2,%3}, [%4];"
                 : "=r"(d[0]), "=r"(d[1]), "=r"(d[2]), "=r"(d[3]) : "r"(addr));
}
__device__ __forceinline__ void mma16816(float* c, const uint32_t* a, const uint32_t* b) {
    asm volatile(
        "mma.sync.aligned.m16n8k16.row.col.f32.f16.f16.f32 "
        "{%0,%1,%2,%3}, {%4,%5,%6,%7}, {%8,%9}, {%0,%1,%2,%3};"
        : "+f"(c[0]), "+f"(c[1]), "+f"(c[2]), "+f"(c[3])
        : "r"(a[0]), "r"(a[1]), "r"(a[2]), "r"(a[3]), "r"(b[0]), "r"(b[1]));
}
#define CP16(sa, ga) \
    asm volatile("cp.async.ca.shared.global [%0], [%1], 16;" :: "r"(sa), "l"(ga))
#define CP_COMMIT() asm volatile("cp.async.commit_group;" ::: "memory")
#define CP_WAIT2()  asm volatile("cp.async.wait_group 2;"  ::: "memory")

// ============================================================================
// Templated fp16 HMMA GEMM:  D[128x128 tile] = A(MxK) * B(NxK)^T * cscale
// 3-stage cp.async pipeline (2x16KB per stage = 96KB smem, 2 CTAs/SM).
// MODE 0: plain.  MODE 1: causal score tile skip — dead tiles write their
//         fp32 zero attn tile to Zattn then exit.
// MODE 2: causal K-limit; row tiles REVERSED (heavy tiles scheduled first).
// OUT 0: fp32.  OUT 1: fp16 (coalesced __half2 stores).
// (R9 mainloop — measured 62.7us / tensor 45% on the 8192x1024x1024.)
// ============================================================================
template<int MODE, int OUT>
__global__ __launch_bounds__(256, 2)
void gemm_t(const __half* __restrict__ Ah, const __half* __restrict__ Bh,
            void* __restrict__ Cout, float* __restrict__ Zattn, float cscale,
            int K, int lda, int ldb, int ldc,
            long long aS1, long long aS2, long long bS1, long long bS2,
            long long cS1, long long cS2)
{
    extern __shared__ char sm[];
    const int tid  = threadIdx.x;
    const int wid  = tid >> 5;
    const int lane = tid & 31;
    const int row0 = (MODE == 2)
        ? ((int)gridDim.y - 1 - (int)blockIdx.y) * 128   // heavy tiles first
        : blockIdx.y * 128;
    const int col0 = blockIdx.x * 128;
    const int z1 = blockIdx.z >> 3, z2 = blockIdx.z & 7;

    if (MODE == 1 && col0 >= row0 + 128) {
        // fully above diagonal: attn is exactly zero here — write it now
        // (rides free under this launch's 3.8%-busy DRAM).
        float* Zb = Zattn + (size_t)z1 * cS1 + (size_t)z2 * cS2
                  + (size_t)row0 * ldc + col0;
        const float4 z4 = make_float4(0.f, 0.f, 0.f, 0.f);
#pragma unroll
        for (int i = 0; i < 16; i++) {
            int id = tid + 256 * i;
            int rr = id >> 5, ccc = (id & 31) * 4;
            *(float4*)(Zb + (size_t)rr * ldc + ccc) = z4;
        }
        return;
    }

    const __half* Ab  = Ah + (size_t)z1 * aS1 + (size_t)z2 * aS2;
    const __half* Bhb = Bh + (size_t)z1 * bS1 + (size_t)z2 * bS2;

    const int Keff = (MODE == 2) ? (row0 + 128 < K ? row0 + 128 : K) : K;
    const int nCh  = Keff >> 6;                      // 64-wide K chunks (>=2)

    const uint32_t sb = smem_u32(sm);

#define FILL(cc) do {                                                         \
        uint32_t stb = sb + (uint32_t)((cc) % 3) * 32768;                     \
        const size_t k0 = (size_t)(cc) << 6;                                  \
        _Pragma("unroll")                                                     \
        for (int i = 0; i < 4; i++) {                                         \
            int id = tid + 256 * i;                                           \
            int rr = id >> 3, sg = id & 7;                                    \
            uint32_t sw = sw128((uint32_t)rr * 128 + sg * 16);                \
            CP16(stb + sw,         Ab  + (size_t)(row0 + rr) * lda + k0 + sg * 8); \
            CP16(stb + 16384 + sw, Bhb + (size_t)(col0 + rr) * ldb + k0 + sg * 8); \
        }                                                                     \
    } while (0)

    // ---- warp tiling: 2 (m) x 4 (n) warps; each 64 rows x 32 cols ----
    const int wm = (wid >> 2) * 64;
    const int wn = (wid & 3) * 32;

    uint32_t aBase[4], bBase[2];
#pragma unroll
    for (int mt = 0; mt < 4; mt++) {
        int r = wm + mt * 16 + ((lane >> 3) & 1) * 8 + (lane & 7);
        aBase[mt] = (uint32_t)r * 128 + (uint32_t)((lane >> 4) * 8) * 2;
    }
#pragma unroll
    for (int np = 0; np < 2; np++) {
        int r = wn + np * 16 + (lane >> 4) * 8 + (lane & 7);
        bBase[np] = (uint32_t)r * 128 + (uint32_t)(((lane >> 3) & 1) * 8) * 2;
    }

    float acc[4][4][4];
#pragma unroll
    for (int mt = 0; mt < 4; mt++)
#pragma unroll
        for (int nt = 0; nt < 4; nt++)
#pragma unroll
            for (int i = 0; i < 4; i++) acc[mt][nt][i] = 0.f;

    // ---- prologue: 3 stages in flight ----
#pragma unroll
    for (int p = 0; p < 3; p++) { if (p < nCh) FILL(p); CP_COMMIT(); }

    for (int c = 0; c < nCh; ++c) {
        CP_WAIT2();
        __syncthreads();
        const uint32_t tb = sb + (uint32_t)(c % 3) * 32768;
#pragma unroll
        for (int ks = 0; ks < 4; ks++) {
            const uint32_t kb2 = (uint32_t)ks * 32;
            uint32_t a[4][4], b2[2][4];
#pragma unroll
            for (int mt = 0; mt < 4; mt++)
                ldm4(a[mt], tb + sw128(aBase[mt] + kb2));
#pragma unroll
            for (int np = 0; np < 2; np++)
                ldm4(b2[np], tb + 16384 + sw128(bBase[np] + kb2));
#pragma unroll
            for (int mt = 0; mt < 4; mt++)
#pragma unroll
                for (int nt = 0; nt < 4; nt++)
                    mma16816(acc[mt][nt], a[mt], &b2[nt >> 1][(nt & 1) * 2]);
        }
        __syncthreads();                // all reads of buf (c%3) done
        int f = c + 3;
        if (f < nCh) FILL(f);
        CP_COMMIT();
    }
#undef FILL

    // ---- epilogue (single variant per instantiation) ----
#pragma unroll
    for (int mt = 0; mt < 4; mt++) {
        const int r = row0 + wm + mt * 16 + (lane >> 2);
#pragma unroll
        for (int nt = 0; nt < 4; nt++) {
            const int cc = col0 + wn + nt * 8 + (lane & 3) * 2;
            float a0 = acc[mt][nt][0], a1 = acc[mt][nt][1];
            float a2 = acc[mt][nt][2], a3 = acc[mt][nt][3];
            if (cscale != 1.f) { a0 *= cscale; a1 *= cscale; a2 *= cscale; a3 *= cscale; }
            if (OUT == 0) {
                float* Cb = (float*)Cout + (size_t)z1 * cS1 + (size_t)z2 * cS2;
                float* p = Cb + (size_t)r * ldc + cc;
                *(float2*)p = make_float2(a0, a1);
                *(float2*)(p + (size_t)8 * ldc) = make_float2(a2, a3);
            } else {
                __half* Cb = (__half*)Cout + (size_t)z1 * cS1 + (size_t)z2 * cS2;
                *(__half2*)(Cb + (size_t)r * ldc + cc) = __floats2half2_rn(a0, a1);
                *(__half2*)(Cb + (size_t)(r + 8) * ldc + cc) = __floats2half2_rn(a2, a3);
            }
        }
    }
}

// ============================================================================
// fp32 -> fp16 convert; blockIdx.y selects one of 3 (in,out) pairs
// ============================================================================
__global__ __launch_bounds__(256)
void conv_h3(const float* __restrict__ i0, __half* __restrict__ o0,
             const float* __restrict__ i1, __half* __restrict__ o1,
             const float* __restrict__ i2, __half* __restrict__ o2)
{
    const float* in  = blockIdx.y == 0 ? i0 : (blockIdx.y == 1 ? i1 : i2);
    __half*      out = blockIdx.y == 0 ? o0 : (blockIdx.y == 1 ? o1 : o2);
    const size_t i = ((size_t)blockIdx.x * 256 + threadIdx.x) * 4;
    float4 v = *(const float4*)(in + i);
    *(__half2*)(out + i)     = __floats2half2_rn(v.x, v.y);
    *(__half2*)(out + i + 2) = __floats2half2_rn(v.z, v.w);
}

// ============================================================================
// Merged weight transpose: z<8 Wq[z], z<16 Wk[z-8], z==16 Wv (all 1024x128),
// z==17 Wo (128x1024, block indices swapped).
// ============================================================================
__global__ __launch_bounds__(256)
void transpose_w18(const float* __restrict__ Wq, const float* __restrict__ Wk,
                   const float* __restrict__ Wv, const float* __restrict__ Wo,
                   __half* __restrict__ wqh, __half* __restrict__ wkh,
                   __half* __restrict__ wvh, __half* __restrict__ woh)
{
    __shared__ float t[32][33];
    const int z = blockIdx.z;
    const float* in; __half* out;
    int R, C, r0, c0;
    if (z < 8)       { in = Wq + (size_t)z * 131072;       out = wqh + (size_t)z * 131072;
                       R = 1024; C = 128; r0 = blockIdx.y * 32; c0 = blockIdx.x * 32; }
    else if (z < 16) { in = Wk + (size_t)(z - 8) * 131072; out = wkh + (size_t)(z - 8) * 131072;
                       R = 1024; C = 128; r0 = blockIdx.y * 32; c0 = blockIdx.x * 32; }
    else if (z == 16){ in = Wv;                            out = wvh;
                       R = 1024; C = 128; r0 = blockIdx.y * 32; c0 = blockIdx.x * 32; }
    else             { in = Wo;                            out = woh;
                       R = 128;  C = 1024; r0 = blockIdx.x * 32; c0 = blockIdx.y * 32; }
    const int tx = threadIdx.x, ty = threadIdx.y;
#pragma unroll
    for (int i = 0; i < 32; i += 8)
        t[ty + i][tx] = in[(size_t)(r0 + ty + i) * C + c0 + tx];
    __syncthreads();
#pragma unroll
    for (int i = 0; i < 32; i += 8)
        out[(size_t)(c0 + ty + i) * R + r0 + tx] = __float2half_rn(t[tx][ty + i]);
}

// ============================================================================
// Combine 4 split-K vh partials (row-major fp16) AND transpose into
// vth[b][d][t]. 32x32 smem tile; coalesced reads and writes. block (32,8).
// vtp[s][(b*1024+t)*128 + d]  ->  vth[b*131072 + d*1024 + t]
// ============================================================================
__global__ __launch_bounds__(256)
void combine_vtp_t(const __half* __restrict__ vtp, __half* __restrict__ vth)
{
    __shared__ float tile[32][33];
    const int d0 = blockIdx.x * 32;        // 0..96
    const int t0 = blockIdx.y * 32;        // 0..992
    const int b  = blockIdx.z;
    const int tx = threadIdx.x, ty = threadIdx.y;
#pragma unroll
    for (int i = 0; i < 32; i += 8) {
        const size_t idx = ((size_t)b * 1024 + t0 + ty + i) * 128 + d0 + tx;
        float s = 0.f;
#pragma unroll
        for (int sl = 0; sl < 4; sl++)
            s += __half2float(vtp[(size_t)sl * 1048576 + idx]);
        tile[ty + i][tx] = s;              // tile[t][d]
    }
    __syncthreads();
#pragma unroll
    for (int i = 0; i < 32; i += 8)
        vth[(size_t)b * 131072 + (size_t)(d0 + ty + i) * 1024 + t0 + tx] =
            __float2half_rn(tile[tx][ty + i]);
}

// ============================================================================
// Causal softmax — four fully-unrolled straight-line bodies selected by
// warp-uniform branches (rows load only ceil-to-256 of their causal range).
// Loads are UNCONDITIONAL and front-batched inside each body (guarded loads
// cost ~33us, see R10/R12). Stores predicated to the causal 128-block edge
// (free). Zeros above the edge come from the scores GEMM's dead tiles.
// One warp per row.
// ============================================================================
template<int NCH>
__device__ __forceinline__ void softmax_body(__half2* __restrict__ srow,
                                             float* __restrict__ arow,
                                             int t, int lane)
{
    float2 v[NCH];
    float m = -1e30f;
#pragma unroll
    for (int i = 0; i < NCH; i++) {
        const int pi = i * 32 + lane;          // half2 index; s = 2*pi, 2*pi+1
        __half2 h = srow[pi];
        v[i].x = (2 * pi     <= t) ? __low2float(h)  : -1e30f;
        v[i].y = (2 * pi + 1 <= t) ? __high2float(h) : -1e30f;
        m = fmaxf(m, fmaxf(v[i].x, v[i].y));
    }
#pragma unroll
    for (int o = 16; o; o >>= 1) m = fmaxf(m, __shfl_xor_sync(~0u, m, o));

    const float scale = 0.08838834764831845f;   // 1/sqrt(128)
    float sum = 0.f;
#pragma unroll
    for (int i = 0; i < NCH; i++) {
        const int pi = i * 32 + lane;
        float e0 = (2 * pi     <= t) ? __expf((v[i].x - m) * scale) : 0.f;
        float e1 = (2 * pi + 1 <= t) ? __expf((v[i].y - m) * scale) : 0.f;
        v[i].x = e0; v[i].y = e1;
        sum += e0 + e1;
    }
#pragma unroll
    for (int o = 16; o; o >>= 1) sum += __shfl_xor_sync(~0u, sum, o);
    const float rinv = 1.0f / sum;

    const int plim = (((t >> 7) + 1) << 6);     // half2 units inside causal blocks
#pragma unroll
    for (int i = 0; i < NCH; i++) {
        const int pi = i * 32 + lane;
        if (pi < plim) {
            float p0 = v[i].x * rinv, p1 = v[i].y * rinv;
            *(float2*)(arow + 2 * pi) = make_float2(p0, p1);
            srow[pi] = __floats2half2_rn(p0, p1);
        }
    }
}

__global__ __launch_bounds__(256)
void softmax_kernel(__half* __restrict__ sc, float* __restrict__ attn)
{
    const int gw   = blockIdx.x * 8 + (threadIdx.x >> 5);
    const int lane = threadIdx.x & 31;
    const int t    = gw & (TT - 1);
    __half2* srow = (__half2*)(sc + (size_t)gw * TT);
    float*   arow = attn + (size_t)gw * TT;

    const int q = t >> 8;                       // 0..3
    if      (q == 0) softmax_body<4>(srow, arow, t, lane);
    else if (q == 1) softmax_body<8>(srow, arow, t, lane);
    else if (q == 2) softmax_body<12>(srow, arow, t, lane);
    else             softmax_body<16>(srow, arow, t, lane);
}

// ============================================================================
// Head mean over fp16 oh -> fp16 om. 2 elems (half2) per thread.
// ============================================================================
__global__ __launch_bounds__(256)
void reduce_mean_h(const __half2* __restrict__ oh, __half2* __restrict__ om)
{
    const size_t i = (size_t)blockIdx.x * 256 + threadIdx.x;   // half2 units
    float sx = 0.f, sy = 0.f;
#pragma unroll
    for (int h = 0; h < NH; h++) {
        __half2 v = oh[(size_t)h * (MROWS * DK / 2) + i];
        sx += __low2float(v);
        sy += __high2float(v);
    }
    om[i] = __floats2half2_rn(sx * 0.125f, sy * 0.125f);
}

// ============================================================================
extern "C" void kernel_launch(void* const* d_in, const int* in_sizes, int n_in,
                              void* d_out, int out_size)
{
    const float* q  = (const float*)d_in[0];
    const float* k  = (const float*)d_in[1];
    const float* v  = (const float*)d_in[2];
    /* d_in[3] = mask: exact causal tril; handled analytically */
    const float* Wq = (const float*)d_in[4];
    const float* Wk = (const float*)d_in[5];
    const float* Wv = (const float*)d_in[6];
    const float* Wo = (const float*)d_in[7];

    float* out  = (float*)d_out;                       // (B,T,DM)
    float* attn = out + (size_t)MROWS * DM;            // (H,B,T,S)

    __half *q2,*k2,*v2,*wqh,*wkh,*wvh,*woh,*qh,*khh,*vtp,*vth,*sc,*oh,*om;
    cudaGetSymbolAddress((void**)&q2,  g_q2);
    cudaGetSymbolAddress((void**)&k2,  g_k2);
    cudaGetSymbolAddress((void**)&v2,  g_v2);
    cudaGetSymbolAddress((void**)&wqh, g_wqh);
    cudaGetSymbolAddress((void**)&wkh, g_wkh);
    cudaGetSymbolAddress((void**)&wvh, g_wvh);
    cudaGetSymbolAddress((void**)&woh, g_woh);
    cudaGetSymbolAddress((void**)&qh,  g_qh);
    cudaGetSymbolAddress((void**)&khh, g_khh);
    cudaGetSymbolAddress((void**)&vtp, g_vtp);
    cudaGetSymbolAddress((void**)&vth, g_vth);
    cudaGetSymbolAddress((void**)&sc,  g_sc);
    cudaGetSymbolAddress((void**)&oh,  g_oh);
    cudaGetSymbolAddress((void**)&om,  g_om);

    const int GSM = 3 * 2 * 16384;                     // 96 KB dynamic smem
    cudaFuncSetAttribute(gemm_t<0,0>, cudaFuncAttributeMaxDynamicSharedMemorySize, GSM);
    cudaFuncSetAttribute(gemm_t<0,1>, cudaFuncAttributeMaxDynamicSharedMemorySize, GSM);
    cudaFuncSetAttribute(gemm_t<1,1>, cudaFuncAttributeMaxDynamicSharedMemorySize, GSM);
    cudaFuncSetAttribute(gemm_t<2,1>, cudaFuncAttributeMaxDynamicSharedMemorySize, GSM);

    dim3 tb(32, 8);

    // ---- operand preparation ----
    conv_h3<<<dim3(MROWS * DM / 1024, 3), 256>>>(q, q2, k, k2, v, v2);
    transpose_w18<<<dim3(4, 32, 18), tb>>>(Wq, Wk, Wv, Wo, wqh, wkh, wvh, woh);

    // ---- Q + K projections, ONE launch (z2 = 0:Q, 1:K via pointer diffs) ----
    const long long dA = (long long)(k2  - q2);        // element diffs
    const long long dB = (long long)(wkh - wqh);
    const long long dC = (long long)(khh - qh);
    gemm_t<0,1><<<dim3(8, 64, 2), 256, GSM>>>(q2, wqh, qh, nullptr, 1.f,
                                              1024, 1024, 1024, 1024,
                                              0, dA, 0, dB, 0, dC);

    // V projection: split-K x4, coalesced row-major partials -> vtp,
    // then fused sum+transpose into vth.
    gemm_t<0,1><<<dim3(1, 64, 4), 256, GSM>>>(v2, wvh, vtp, nullptr, 1.f,
                                              256, 1024, 1024, 128,
                                              0, 256LL,             // A: +k slab
                                              0, 256LL,             // B: +k slab
                                              0, 1048576LL);        // C: partial
    combine_vtp_t<<<dim3(4, 32, 8), tb>>>(vtp, vth);

    // ---- scores = qh @ kh^T -> fp16 sc; dead tiles zero-fill attn ----
    gemm_t<1,1><<<dim3(8, 8, 64), 256, GSM>>>(qh, khh, sc, attn, 1.f,
                                              128, 1024, 1024, 1024,
                                              1048576LL, 128LL,      // A: b, h
                                              1048576LL, 128LL,      // B: b, h
                                              1048576LL, 8388608LL); // C: b, h

    // ---- softmax: sc(fp16) -> attn(fp32, causal range) + P into sc ----
    softmax_kernel<<<dim3(NH * BB * TT / 8), 256>>>(sc, attn);

    // ---- O_h = P @ V  (per-head, causal K limit, heavy rows first) ----
    gemm_t<2,1><<<dim3(1, 8, 64), 256, GSM>>>(sc, vth, oh, nullptr, 1.f,
                                              1024, 1024, 1024, 128,
                                              1048576LL, 8388608LL,  // A: b, h
                                              131072LL,  0LL,        // B: b
                                              131072LL,  1048576LL); // C: b, h

    // ---- head mean (fp16 in/out) ----
    reduce_mean_h<<<dim3((MROWS * DK / 2) / 256), 256>>>(
        (const __half2*)oh, (__half2*)om);

    // ---- out = Om @ Wo ----
    gemm_t<0,0><<<dim3(8, 64, 1), 256, GSM>>>(om, woh, out, nullptr, 1.f,
                                              128, 128, 128, 1024,
                                              0,0, 0,0, 0,0);
}